// round 10
// baseline (speedup 1.0000x reference)
#include <cuda_runtime.h>
#include <cuda_bf16.h>
#include <cuda_fp16.h>
#include <stdint.h>

#define B_ 512
#define T_ 32
#define D_ 512
#define M_ 1024
#define N_ (B_*T_)          // 16384

// ---------------- scratch (fp8 operand buffers) ----------------
__device__ __align__(16) uint8_t g_a8[N_*D_];      // e4m3(x)
__device__ __align__(16) uint8_t g_v8[N_*D_];
__device__ __align__(16) uint8_t g_e8[M_*D_];      // e4m3(e*4096)
__device__ float g_an[N_];
__device__ float g_vn[N_];
__device__ float g_en[M_];
__device__ __align__(16) uint8_t g_sd8_a[N_*M_];   // e4m3(sd-22)
__device__ __align__(16) uint8_t g_sd8_v[N_*M_];
__device__ __align__(16) uint8_t g_adj8_a[N_*M_];  // e4m3(adj*1024)
__device__ __align__(16) uint8_t g_adj8_v[N_*M_];
__device__ float g_L_a[N_];                        // L' = lse(-(sd-22)) per row
__device__ float g_L_v[N_];
__device__ float g_rowsum[2*T_*B_];
__device__ float g_diag[2*T_*B_];
__device__ double g_part[64];

// ---------------- helpers ----------------
__device__ __forceinline__ float warpRedSum(float v){
  #pragma unroll
  for (int o=16;o>0;o>>=1) v += __shfl_xor_sync(0xffffffffu, v, o);
  return v;
}
__device__ __forceinline__ float warpRedMin(float v){
  #pragma unroll
  for (int o=16;o>0;o>>=1) v = fminf(v, __shfl_xor_sync(0xffffffffu, v, o));
  return v;
}
__device__ float blockSum(float v){
  __shared__ float sm[32]; __shared__ float res;
  int lane = threadIdx.x & 31, w = threadIdx.x >> 5, nw = blockDim.x >> 5;
  v = warpRedSum(v);
  if (!lane) sm[w] = v;
  __syncthreads();
  if (w == 0){
    float t = (lane < nw) ? sm[lane] : 0.f;
    t = warpRedSum(t);
    if (!lane) res = t;
  }
  __syncthreads();
  return res;
}

__device__ __forceinline__ unsigned short pack2_e4m3(float lo, float hi){
  unsigned short r;
  asm("cvt.rn.satfinite.e4m3x2.f32 %0, %1, %2;" : "=h"(r) : "f"(hi), "f"(lo));
  return r;
}
__device__ __forceinline__ void unpack4_e4m3(uint32_t u, float* f){
  uint32_t h01, h23;
  asm("{\n\t.reg .b16 lo, hi;\n\tmov.b32 {lo, hi}, %2;\n\t"
      "cvt.rn.f16x2.e4m3x2 %0, lo;\n\tcvt.rn.f16x2.e4m3x2 %1, hi;\n\t}"
      : "=r"(h01), "=r"(h23) : "r"(u));
  __half2 a = *(__half2*)&h01, b = *(__half2*)&h23;
  float2 fa = __half22float2(a), fb = __half22float2(b);
  f[0]=fa.x; f[1]=fa.y; f[2]=fb.x; f[3]=fb.y;
}

__global__ void k_zero(float* rs){ rs[blockIdx.x*512 + threadIdx.x] = 0.f; }

// ---------------- convert fp32 -> e4m3 (scaled) + row sq-norm (warp per row) ----------------
__global__ void k_prep(const float* __restrict__ a, const float* __restrict__ v,
                       const float* __restrict__ e,
                       uint8_t* __restrict__ a8, uint8_t* __restrict__ v8,
                       uint8_t* __restrict__ e8,
                       float* __restrict__ an, float* __restrict__ vn,
                       float* __restrict__ en){
  int row = blockIdx.x*8 + (threadIdx.x >> 5);
  int lane = threadIdx.x & 31;
  const float* x; uint8_t* xb; float* nrm; int r; float sc;
  if (row < N_){ x=a; xb=a8; nrm=an; r=row; sc=1.f; }
  else if (row < 2*N_){ x=v; xb=v8; nrm=vn; r=row-N_; sc=1.f; }
  else { x=e; xb=e8; nrm=en; r=row-2*N_; sc=4096.f; }
  const float4* src = (const float4*)(x + (size_t)r * D_);
  uint32_t* dst = (uint32_t*)(xb + (size_t)r * D_);
  float s = 0.f;
  #pragma unroll
  for (int i=0;i<4;i++){
    float4 f = src[lane + 32*i];
    s += f.x*f.x + f.y*f.y + f.z*f.z + f.w*f.w;
    unsigned short p0 = pack2_e4m3(f.x*sc, f.y*sc);
    unsigned short p1 = pack2_e4m3(f.z*sc, f.w*sc);
    dst[lane + 32*i] = (uint32_t)p0 | ((uint32_t)p1 << 16);
  }
  s = warpRedSum(s);
  if (!lane) nrm[r] = s;
}

// ---------------- FP8 HMMA machinery ----------------
__device__ __forceinline__ void cpa16(uint32_t s, const void* g){
  asm volatile("cp.async.cg.shared.global [%0], [%1], 16;" :: "r"(s), "l"(g));
}
__device__ __forceinline__ void ldmx4(uint32_t* r, uint32_t a){
  asm volatile("ldmatrix.sync.aligned.m8n8.x4.shared.b16 {%0,%1,%2,%3}, [%4];"
    : "=r"(r[0]), "=r"(r[1]), "=r"(r[2]), "=r"(r[3]) : "r"(a));
}
__device__ __forceinline__ void mma_fp8(float* c, const uint32_t* a, uint32_t b0, uint32_t b1){
  asm volatile("mma.sync.aligned.m16n8k32.row.col.f32.e4m3.e4m3.f32 "
    "{%0,%1,%2,%3}, {%4,%5,%6,%7}, {%8,%9}, {%0,%1,%2,%3};"
    : "+f"(c[0]), "+f"(c[1]), "+f"(c[2]), "+f"(c[3])
    : "r"(a[0]), "r"(a[1]), "r"(a[2]), "r"(a[3]), "r"(b0), "r"(b1));
}

// CTA tile 128(M) x 128(N), K-chunk = 128 fp8 (128B rows). 128 threads, 4 warps
// (2M x 2N), warp tile 64x64. NBUF=3 (96KB) -> 2 CTAs/SM. One barrier per chunk.
#define NBUF 3
#define ABYTES 16384
#define STG 32768
#define SMEM_DYN (NBUF*STG)   // 96KB

__device__ __forceinline__ void g_load(uint32_t sbase, int st, int ck,
                                       const char* Ab, const char* Bb,
                                       long ldab, long ldbb, int tid){
  uint32_t dA = sbase + (uint32_t)st * STG;
  uint32_t dB = dA + ABYTES;
  long koff = (long)ck * 128;
  #pragma unroll
  for (int i=0;i<8;i++){
    int idx = tid + (i<<7); int r = idx >> 3, c = idx & 7;
    uint32_t off = (uint32_t)(r*128 + ((c ^ (r&7))<<4));
    cpa16(dA + off, Ab + (long)r*ldab + koff + c*16);
  }
  #pragma unroll
  for (int i=0;i<8;i++){
    int idx = tid + (i<<7); int r = idx >> 3, c = idx & 7;
    uint32_t off = (uint32_t)(r*128 + ((c ^ (r&7))<<4));
    cpa16(dB + off, Bb + (long)r*ldbb + koff + c*16);
  }
  asm volatile("cp.async.commit_group;");
}

__device__ __forceinline__ void ld_frags(uint32_t aB, uint32_t bB, int ks,
                                         int wm, int wn, int lane,
                                         uint32_t af[4][4], uint32_t bfr[4][4]){
  #pragma unroll
  for (int mi=0; mi<4; ++mi){
    int row = wm + mi*16 + (lane & 15);
    int ch  = 2*ks + (lane >> 4);
    ldmx4(af[mi], aB + (uint32_t)(row*128 + ((ch ^ (row&7))<<4)));
  }
  #pragma unroll
  for (int p=0; p<4; ++p){
    int row = wn + p*16 + ((lane>>4)<<3) + (lane&7);
    int ch  = 2*ks + ((lane>>3)&1);
    ldmx4(bfr[p], bB + (uint32_t)(row*128 + ((ch ^ (row&7))<<4)));
  }
}

template<int KT>
__device__ __forceinline__ void g_main(uint32_t sbase, const char* Ab, const char* Bb,
                                       long ldab, long ldbb,
                                       float acc[4][8][4], int tid, int lane,
                                       int wm, int wn){
  g_load(sbase, 0, 0, Ab, Bb, ldab, ldbb, tid);
  g_load(sbase, 1, 1, Ab, Bb, ldab, ldbb, tid);
  #pragma unroll 1
  for (int kt = 0; kt < KT; ++kt){
    asm volatile("cp.async.wait_group 1;");
    __syncthreads();
    if (kt+2 < KT){
      int st = (kt+2)%3;
      g_load(sbase, st, kt+2, Ab, Bb, ldab, ldbb, tid);
    } else {
      asm volatile("cp.async.commit_group;");
    }
    uint32_t aB = sbase + (uint32_t)(kt%3) * STG;
    uint32_t bB = aB + ABYTES;
    uint32_t af[2][4][4], bfr[2][4][4];
    ld_frags(aB, bB, 0, wm, wn, lane, af[0], bfr[0]);
    #pragma unroll
    for (int ks=0; ks<4; ++ks){
      int cur = ks & 1, nxt = cur ^ 1;
      if (ks < 3) ld_frags(aB, bB, ks+1, wm, wn, lane, af[nxt], bfr[nxt]);
      #pragma unroll
      for (int mi=0; mi<4; ++mi)
        #pragma unroll
        for (int ni=0; ni<8; ++ni){
          const uint32_t* bp = bfr[cur][ni>>1];
          uint32_t b0 = (ni&1) ? bp[2] : bp[0];
          uint32_t b1 = (ni&1) ? bp[3] : bp[1];
          mma_fp8(acc[mi][ni], af[cur][mi], b0, b1);
        }
    }
  }
}

// ---------------- GEMM1: sd8 = e4m3(sqrt(max(rn+cn-2*dot,0)) - 22) ----------------
// dot = acc/4096 (e operand pre-scaled by 4096)
__global__ void __launch_bounds__(128, 2)
k_g1(const uint8_t* __restrict__ A0, const uint8_t* __restrict__ A1,
     const uint8_t* __restrict__ E,
     uint8_t* __restrict__ C0, uint8_t* __restrict__ C1,
     const float* __restrict__ rn0, const float* __restrict__ rn1,
     const float* __restrict__ cn)
{
  extern __shared__ char dsm[];
  uint32_t sbase = (uint32_t)__cvta_generic_to_shared(dsm);
  const int tid = threadIdx.x, lane = tid & 31, warp = tid >> 5;
  const int wm = (warp & 1) * 64, wn = (warp >> 1) * 64;
  const int z = blockIdx.z;
  const uint8_t* A = z ? A1 : A0;
  const float* rn = z ? rn1 : rn0;
  uint8_t* C = z ? C1 : C0;

  const char* Ab = (const char*)A + (long)blockIdx.y * 128 * 512;
  const char* Bb = (const char*)E + (long)blockIdx.x * 128 * 512;

  float acc[4][8][4];
  #pragma unroll
  for (int a=0;a<4;a++)
    #pragma unroll
    for (int b=0;b<8;b++)
      #pragma unroll
      for (int c=0;c<4;c++) acc[a][b][c]=0.f;

  g_main<4>(sbase, Ab, Bb, 512, 512, acc, tid, lane, wm, wn);

  const float ds = -2.f/4096.f;
  const int tr = lane >> 2, tc = (lane & 3) * 2;
  #pragma unroll
  for (int mi=0; mi<4; ++mi){
    int r0 = blockIdx.y*128 + wm + mi*16 + tr;
    float rn0v = rn[r0], rn1v = rn[r0+8];
    #pragma unroll
    for (int ni=0; ni<8; ++ni){
      int col = blockIdx.x*128 + wn + ni*8 + tc;
      float c0 = cn[col], c1 = cn[col+1];
      float* a = acc[mi][ni];
      float s00 = sqrtf(fmaxf(fmaf(ds, a[0], rn0v + c0), 0.f)) - 22.f;
      float s01 = sqrtf(fmaxf(fmaf(ds, a[1], rn0v + c1), 0.f)) - 22.f;
      float s10 = sqrtf(fmaxf(fmaf(ds, a[2], rn1v + c0), 0.f)) - 22.f;
      float s11 = sqrtf(fmaxf(fmaf(ds, a[3], rn1v + c1), 0.f)) - 22.f;
      *(unsigned short*)&C[(long)r0*M_ + col]     = pack2_e4m3(s00, s01);
      *(unsigned short*)&C[(long)(r0+8)*M_ + col] = pack2_e4m3(s10, s11);
    }
  }
}

// ---------------- softmax (warp per row) on fp8 sdm22: adj8 = e4m3(1024*softmax(-2v)), L' = lse(-v) ----------------
__global__ void __launch_bounds__(256)
k_softmax2(const uint8_t* __restrict__ sda, const uint8_t* __restrict__ sdv,
           uint8_t* __restrict__ adja, uint8_t* __restrict__ adjv,
           float* __restrict__ La, float* __restrict__ Lv){
  int rowg = blockIdx.x*8 + (threadIdx.x >> 5);
  int lane = threadIdx.x & 31;
  int which = rowg >> 14;
  int row = rowg & (N_-1);
  const uint8_t* sd = which ? sdv : sda;
  uint8_t* adj = which ? adjv : adja;
  float* L = which ? Lv : La;
  size_t base = (size_t)row * M_;
  const uint32_t* src = (const uint32_t*)(sd + base);   // 256 u32 per row
  uint32_t* dst = (uint32_t*)(adj + base);

  float v[32];
  float vmin = 3.4e38f;
  #pragma unroll
  for (int j=0;j<8;j++){
    unpack4_e4m3(src[lane + 32*j], &v[4*j]);
    vmin = fminf(vmin, fminf(fminf(v[4*j],v[4*j+1]), fminf(v[4*j+2],v[4*j+3])));
  }
  float rmin = warpRedMin(vmin);
  float s1 = 0.f, s2 = 0.f;
  #pragma unroll
  for (int k=0;k<32;k++){
    float e = __expf(rmin - v[k]);
    v[k] = e;
    s1 += e; s2 += e*e;
  }
  s1 = warpRedSum(s1);
  s2 = warpRedSum(s2);
  float i2 = 1024.0f/s2;
  #pragma unroll
  for (int j=0;j<8;j++){
    float e0=v[4*j], e1=v[4*j+1], e2=v[4*j+2], e3=v[4*j+3];
    unsigned short p0 = pack2_e4m3(e0*e0*i2, e1*e1*i2);
    unsigned short p1 = pack2_e4m3(e2*e2*i2, e3*e3*i2);
    dst[lane + 32*j] = (uint32_t)p0 | ((uint32_t)p1 << 16);
  }
  if (!lane) L[row] = logf(s1) - rmin;   // L' in sdm22 domain
}

// ---------------- GEMM2 + fused loss epilogue ----------------
// p = exp(-acc/1024 - L'[j])  (row-constant factors cancel in diag/denom)
__global__ void __launch_bounds__(128, 2)
k_g2(const uint8_t* __restrict__ adjA, const uint8_t* __restrict__ adjV,
     const uint8_t* __restrict__ sdA,  const uint8_t* __restrict__ sdV,
     const float* __restrict__ La, const float* __restrict__ Lv,
     float* __restrict__ rowsum, float* __restrict__ diag)
{
  extern __shared__ char dsm[];
  uint32_t sbase = (uint32_t)__cvta_generic_to_shared(dsm);
  const int tid = threadIdx.x, lane = tid & 31, warp = tid >> 5;
  const int wm = (warp & 1) * 64, wn = (warp >> 1) * 64;
  const int pair = blockIdx.z >> 5, t = blockIdx.z & 31;
  const uint8_t* A = pair ? adjV : adjA;
  const uint8_t* Bm = pair ? sdA : sdV;
  const float* L = pair ? La : Lv;

  const char* Ab = (const char*)A + (long)t*1024 + (long)blockIdx.y * 128 * 32768;
  const char* Bb = (const char*)Bm + (long)t*1024 + (long)blockIdx.x * 128 * 32768;

  float acc[4][8][4];
  #pragma unroll
  for (int a=0;a<4;a++)
    #pragma unroll
    for (int b=0;b<8;b++)
      #pragma unroll
      for (int c=0;c<4;c++) acc[a][b][c]=0.f;

  g_main<8>(sbase, Ab, Bb, 32768, 32768, acc, tid, lane, wm, wn);

  __syncthreads();
  float* Lsm = (float*)dsm;     // 128 floats
  Lsm[tid] = L[(long)(blockIdx.x*128 + tid)*T_ + t];
  __syncthreads();

  const float as = -1.f/1024.f;
  const int tr = lane >> 2, tc = (lane & 3) * 2;
  const int batch = pair*T_ + t;
  float* dout = diag + (long)batch * B_;
  float rp[8];
  #pragma unroll
  for (int i=0;i<8;i++) rp[i]=0.f;
  #pragma unroll
  for (int mi=0; mi<4; ++mi){
    int gi0 = blockIdx.y*128 + wm + mi*16 + tr;
    #pragma unroll
    for (int ni=0; ni<8; ++ni){
      int lc = wn + ni*8 + tc;
      int gj = blockIdx.x*128 + lc;
      float L0 = Lsm[lc], L1 = Lsm[lc+1];
      float* a = acc[mi][ni];
      float p00 = __expf(fmaf(as, a[0], -L0)), p01 = __expf(fmaf(as, a[1], -L1));
      float p10 = __expf(fmaf(as, a[2], -L0)), p11 = __expf(fmaf(as, a[3], -L1));
      rp[mi*2]   += p00 + p01;
      rp[mi*2+1] += p10 + p11;
      if (gj   == gi0)   dout[gi0]   = p00;
      if (gj+1 == gi0)   dout[gi0]   = p01;
      if (gj   == gi0+8) dout[gi0+8] = p10;
      if (gj+1 == gi0+8) dout[gi0+8] = p11;
    }
  }
  #pragma unroll
  for (int i=0;i<8;i++){
    rp[i] += __shfl_xor_sync(0xffffffffu, rp[i], 1);
    rp[i] += __shfl_xor_sync(0xffffffffu, rp[i], 2);
  }
  __syncthreads();
  float* part = (float*)dsm + 128;
  int ng = warp >> 1;
  if ((lane & 3) == 0){
    #pragma unroll
    for (int mi=0; mi<4; ++mi){
      int r = wm + mi*16 + tr;
      part[r*2 + ng]     = rp[mi*2];
      part[(r+8)*2 + ng] = rp[mi*2+1];
    }
  }
  __syncthreads();
  {
    float s = part[tid*2] + part[tid*2+1];
    atomicAdd(&rowsum[(long)batch*B_ + blockIdx.y*128 + tid], s);
  }
}

// ---------------- loss partials and final mean ----------------
__global__ void k_loss2(const float* __restrict__ rs, const float* __restrict__ dg,
                        double* __restrict__ part){
  long base = (long)blockIdx.x * B_;
  float term = 0.f;
  #pragma unroll
  for (int h=0; h<2; ++h){
    long i = base + threadIdx.x + h*256;
    term += logf(rs[i]) - logf(dg[i]);
  }
  float s = blockSum(term);
  if (threadIdx.x == 0) part[blockIdx.x] = (double)s;
}
__global__ void k_final(const double* __restrict__ part, float* __restrict__ out){
  double s = (threadIdx.x < 64) ? part[threadIdx.x] : 0.0;
  #pragma unroll
  for (int o=16;o>0;o>>=1) s += __shfl_xor_sync(0xffffffffu, s, o);
  __shared__ double sm[2];
  if ((threadIdx.x & 31) == 0) sm[threadIdx.x>>5] = s;
  __syncthreads();
  if (threadIdx.x == 0) out[0] = (float)((sm[0]+sm[1]) / 32768.0);
}

// ---------------- launch ----------------
extern "C" void kernel_launch(void* const* d_in, const int* in_sizes, int n_in,
                              void* d_out, int out_size)
{
  const float* a = (const float*)d_in[0];
  const float* v = (const float*)d_in[1];
  const float* e = (const float*)d_in[2];
  float* out = (float*)d_out;

  uint8_t *pa, *pv, *pe, *psa, *psv, *paa, *pav;
  float *pan, *pvn, *pen, *pLa, *pLv, *prs, *pdg;
  double *ppt;
  cudaGetSymbolAddress((void**)&pa,  g_a8);
  cudaGetSymbolAddress((void**)&pv,  g_v8);
  cudaGetSymbolAddress((void**)&pe,  g_e8);
  cudaGetSymbolAddress((void**)&pan, g_an);
  cudaGetSymbolAddress((void**)&pvn, g_vn);
  cudaGetSymbolAddress((void**)&pen, g_en);
  cudaGetSymbolAddress((void**)&psa, g_sd8_a);
  cudaGetSymbolAddress((void**)&psv, g_sd8_v);
  cudaGetSymbolAddress((void**)&paa, g_adj8_a);
  cudaGetSymbolAddress((void**)&pav, g_adj8_v);
  cudaGetSymbolAddress((void**)&pLa, g_L_a);
  cudaGetSymbolAddress((void**)&pLv, g_L_v);
  cudaGetSymbolAddress((void**)&prs, g_rowsum);
  cudaGetSymbolAddress((void**)&pdg, g_diag);
  cudaGetSymbolAddress((void**)&ppt, g_part);

  cudaFuncSetAttribute(k_g1, cudaFuncAttributeMaxDynamicSharedMemorySize, SMEM_DYN);
  cudaFuncSetAttribute(k_g2, cudaFuncAttributeMaxDynamicSharedMemorySize, SMEM_DYN);

  k_zero<<<64, 512>>>(prs);
  k_prep<<<(2*N_+M_)/8, 256>>>(a, v, e, pa, pv, pe, pan, pvn, pen);

  dim3 g1(M_/128, N_/128, 2);
  k_g1<<<g1, 128, SMEM_DYN>>>(pa, pv, pe, psa, psv, pan, pvn, pen);

  k_softmax2<<<2*N_/8, 256>>>(psa, psv, paa, pav, pLa, pLv);

  dim3 g2(B_/128, B_/128, 64);
  k_g2<<<g2, 128, SMEM_DYN>>>(paa, pav, psa, psv, pLa, pLv, prs, pdg);

  k_loss2<<<64, 256>>>(prs, pdg, ppt);
  k_final<<<1, 64>>>(ppt, out);
}

// round 11
// speedup vs baseline: 1.1049x; 1.1049x over previous
#include <cuda_runtime.h>
#include <cuda_bf16.h>
#include <stdint.h>

#define B_ 512
#define T_ 32
#define D_ 512
#define M_ 1024
#define N_ (B_*T_)          // 16384

// ---------------- scratch ----------------
__device__ __align__(16) __nv_bfloat16 g_a_bf[N_*D_];
__device__ __align__(16) __nv_bfloat16 g_v_bf[N_*D_];
__device__ __align__(16) __nv_bfloat16 g_e_bf[M_*D_];
__device__ float g_an[N_];
__device__ float g_vn[N_];
__device__ float g_en[M_];
__device__ __align__(16) __nv_bfloat16 g_sd_a[N_*M_];
__device__ __align__(16) __nv_bfloat16 g_sd_v[N_*M_];
__device__ __align__(16) __nv_bfloat16 g_adj_a[N_*M_];
__device__ __align__(16) __nv_bfloat16 g_adj_v[N_*M_];
__device__ float g_L_a[N_];
__device__ float g_L_v[N_];
__device__ float g_rowsum[2*T_*B_];
__device__ float g_diag[2*T_*B_];     // log-domain: S_ii
__device__ double g_part[64];

// ---------------- reduction helpers ----------------
__device__ __forceinline__ float warpRedSum(float v){
  #pragma unroll
  for (int o=16;o>0;o>>=1) v += __shfl_xor_sync(0xffffffffu, v, o);
  return v;
}
__device__ __forceinline__ float warpRedMin(float v){
  #pragma unroll
  for (int o=16;o>0;o>>=1) v = fminf(v, __shfl_xor_sync(0xffffffffu, v, o));
  return v;
}
__device__ float blockSum(float v){
  __shared__ float sm[32]; __shared__ float res;
  int lane = threadIdx.x & 31, w = threadIdx.x >> 5, nw = blockDim.x >> 5;
  v = warpRedSum(v);
  if (!lane) sm[w] = v;
  __syncthreads();
  if (w == 0){
    float t = (lane < nw) ? sm[lane] : 0.f;
    t = warpRedSum(t);
    if (!lane) res = t;
  }
  __syncthreads();
  return res;
}

// ---------------- merged convert + row sq-norm + rowsum zeroing ----------------
__global__ void k_prep(const float* __restrict__ a, const float* __restrict__ v,
                       const float* __restrict__ e,
                       __nv_bfloat16* __restrict__ ab, __nv_bfloat16* __restrict__ vb,
                       __nv_bfloat16* __restrict__ eb,
                       float* __restrict__ an, float* __restrict__ vn,
                       float* __restrict__ en, float* __restrict__ rs){
  // first 64 blocks also zero the 32768-entry rowsum accumulator
  if (blockIdx.x < 64){
    int base = blockIdx.x*512 + threadIdx.x;
    rs[base] = 0.f; rs[base+256] = 0.f;
  }
  int row = blockIdx.x*8 + (threadIdx.x >> 5);
  int lane = threadIdx.x & 31;
  const float* x; __nv_bfloat16* xb; float* nrm; int r;
  if (row < N_){ x=a; xb=ab; nrm=an; r=row; }
  else if (row < 2*N_){ x=v; xb=vb; nrm=vn; r=row-N_; }
  else { x=e; xb=eb; nrm=en; r=row-2*N_; }
  const float4* src = (const float4*)(x + (size_t)r * D_);
  uint2* dst = (uint2*)(xb + (size_t)r * D_);
  float s = 0.f;
  #pragma unroll
  for (int i=0;i<4;i++){
    float4 f = src[lane + 32*i];
    s += f.x*f.x + f.y*f.y + f.z*f.z + f.w*f.w;
    __nv_bfloat162 h0 = __floats2bfloat162_rn(f.x, f.y);
    __nv_bfloat162 h1 = __floats2bfloat162_rn(f.z, f.w);
    uint2 o; o.x = *(unsigned*)&h0; o.y = *(unsigned*)&h1;
    dst[lane + 32*i] = o;
  }
  s = warpRedSum(s);
  if (!lane) nrm[r] = s;
}

// ---------------- HMMA machinery ----------------
__device__ __forceinline__ void cpa16(uint32_t s, const void* g){
  asm volatile("cp.async.cg.shared.global [%0], [%1], 16;" :: "r"(s), "l"(g));
}
__device__ __forceinline__ void ldmx4(uint32_t* r, uint32_t a){
  asm volatile("ldmatrix.sync.aligned.m8n8.x4.shared.b16 {%0,%1,%2,%3}, [%4];"
    : "=r"(r[0]), "=r"(r[1]), "=r"(r[2]), "=r"(r[3]) : "r"(a));
}
__device__ __forceinline__ void mma_bf16(float* c, const uint32_t* a, uint32_t b0, uint32_t b1){
  asm volatile("mma.sync.aligned.m16n8k16.row.col.f32.bf16.bf16.f32 "
    "{%0,%1,%2,%3}, {%4,%5,%6,%7}, {%8,%9}, {%0,%1,%2,%3};"
    : "+f"(c[0]), "+f"(c[1]), "+f"(c[2]), "+f"(c[3])
    : "r"(a[0]), "r"(a[1]), "r"(a[2]), "r"(a[3]), "r"(b0), "r"(b1));
}

// CTA tile 128(M) x 128(N), BK=64 (128B rows). 128 threads, 4 warps (2M x 2N),
// warp tile 64x64. NBUF=3 (96KB) -> 2 CTAs/SM. One barrier per K-chunk.
// Fragment double-buffering: ks+1 frag loads overlap ks MMAs.
#define NBUF 3
#define ABYTES 16384
#define STG 32768
#define SMEM_DYN (NBUF*STG)   // 96KB

__device__ __forceinline__ void g_load(uint32_t sbase, int st, int ck,
                                       const char* Ab, const char* Bb,
                                       long ldab, long ldbb, int tid){
  uint32_t dA = sbase + (uint32_t)st * STG;
  uint32_t dB = dA + ABYTES;
  long koff = (long)ck * 128;
  #pragma unroll
  for (int i=0;i<8;i++){
    int idx = tid + (i<<7); int r = idx >> 3, c = idx & 7;
    uint32_t off = (uint32_t)(r*128 + ((c ^ (r&7))<<4));
    cpa16(dA + off, Ab + (long)r*ldab + koff + c*16);
  }
  #pragma unroll
  for (int i=0;i<8;i++){
    int idx = tid + (i<<7); int r = idx >> 3, c = idx & 7;
    uint32_t off = (uint32_t)(r*128 + ((c ^ (r&7))<<4));
    cpa16(dB + off, Bb + (long)r*ldbb + koff + c*16);
  }
  asm volatile("cp.async.commit_group;");
}

__device__ __forceinline__ void ld_frags(uint32_t aB, uint32_t bB, int ks,
                                         int wm, int wn, int lane,
                                         uint32_t af[4][4], uint32_t bfr[4][4]){
  #pragma unroll
  for (int mi=0; mi<4; ++mi){
    int row = wm + mi*16 + (lane & 15);
    int ch  = 2*ks + (lane >> 4);
    ldmx4(af[mi], aB + (uint32_t)(row*128 + ((ch ^ (row&7))<<4)));
  }
  #pragma unroll
  for (int p=0; p<4; ++p){
    int row = wn + p*16 + ((lane>>4)<<3) + (lane&7);
    int ch  = 2*ks + ((lane>>3)&1);
    ldmx4(bfr[p], bB + (uint32_t)(row*128 + ((ch ^ (row&7))<<4)));
  }
}

template<int KT>
__device__ __forceinline__ void g_main(uint32_t sbase, const char* Ab, const char* Bb,
                                       long ldab, long ldbb,
                                       float acc[4][8][4], int tid, int lane,
                                       int wm, int wn){
  g_load(sbase, 0, 0, Ab, Bb, ldab, ldbb, tid);
  g_load(sbase, 1, 1, Ab, Bb, ldab, ldbb, tid);
  #pragma unroll 1
  for (int kt = 0; kt < KT; ++kt){
    asm volatile("cp.async.wait_group 1;");
    __syncthreads();
    if (kt+2 < KT){
      int st = (kt+2)%3;
      g_load(sbase, st, kt+2, Ab, Bb, ldab, ldbb, tid);
    } else {
      asm volatile("cp.async.commit_group;");
    }
    uint32_t aB = sbase + (uint32_t)(kt%3) * STG;
    uint32_t bB = aB + ABYTES;
    uint32_t af[2][4][4], bfr[2][4][4];
    ld_frags(aB, bB, 0, wm, wn, lane, af[0], bfr[0]);
    #pragma unroll
    for (int ks=0; ks<4; ++ks){
      int cur = ks & 1, nxt = cur ^ 1;
      if (ks < 3) ld_frags(aB, bB, ks+1, wm, wn, lane, af[nxt], bfr[nxt]);
      #pragma unroll
      for (int mi=0; mi<4; ++mi)
        #pragma unroll
        for (int ni=0; ni<8; ++ni){
          const uint32_t* bp = bfr[cur][ni>>1];
          uint32_t b0 = (ni&1) ? bp[2] : bp[0];
          uint32_t b1 = (ni&1) ? bp[3] : bp[1];
          mma_bf16(acc[mi][ni], af[cur][mi], b0, b1);
        }
    }
  }
}

// ---------------- GEMM1: sd = bf16(sqrt(max(rn+cn-2*A.E^T,0))), both modalities ----------------
__global__ void __launch_bounds__(128, 2)
k_g1(const __nv_bfloat16* __restrict__ A0, const __nv_bfloat16* __restrict__ A1,
     const __nv_bfloat16* __restrict__ E,
     __nv_bfloat16* __restrict__ C0, __nv_bfloat16* __restrict__ C1,
     const float* __restrict__ rn0, const float* __restrict__ rn1,
     const float* __restrict__ cn)
{
  extern __shared__ char dsm[];
  uint32_t sbase = (uint32_t)__cvta_generic_to_shared(dsm);
  const int tid = threadIdx.x, lane = tid & 31, warp = tid >> 5;
  const int wm = (warp & 1) * 64, wn = (warp >> 1) * 64;
  const int z = blockIdx.z;
  const __nv_bfloat16* A = z ? A1 : A0;
  const float* rn = z ? rn1 : rn0;
  __nv_bfloat16* C = z ? C1 : C0;

  const char* Ab = (const char*)A + (long)blockIdx.y * 128 * 1024;
  const char* Bb = (const char*)E + (long)blockIdx.x * 128 * 1024;

  float acc[4][8][4];
  #pragma unroll
  for (int a=0;a<4;a++)
    #pragma unroll
    for (int b=0;b<8;b++)
      #pragma unroll
      for (int c=0;c<4;c++) acc[a][b][c]=0.f;

  g_main<8>(sbase, Ab, Bb, 1024, 1024, acc, tid, lane, wm, wn);

  const int tr = lane >> 2, tc = (lane & 3) * 2;
  #pragma unroll
  for (int mi=0; mi<4; ++mi){
    int r0 = blockIdx.y*128 + wm + mi*16 + tr;
    float rn0v = rn[r0], rn1v = rn[r0+8];
    #pragma unroll
    for (int ni=0; ni<8; ++ni){
      int col = blockIdx.x*128 + wn + ni*8 + tc;
      float c0 = cn[col], c1 = cn[col+1];
      float* a = acc[mi][ni];
      __nv_bfloat162 o0 = __floats2bfloat162_rn(
          sqrtf(fmaxf(fmaf(-2.f, a[0], rn0v + c0), 0.f)),
          sqrtf(fmaxf(fmaf(-2.f, a[1], rn0v + c1), 0.f)));
      __nv_bfloat162 o1 = __floats2bfloat162_rn(
          sqrtf(fmaxf(fmaf(-2.f, a[2], rn1v + c0), 0.f)),
          sqrtf(fmaxf(fmaf(-2.f, a[3], rn1v + c1), 0.f)));
      *(__nv_bfloat162*)&C[(long)r0*M_ + col] = o0;
      *(__nv_bfloat162*)&C[(long)(r0+8)*M_ + col] = o1;
    }
  }
}

// ---------------- softmax (warp per row): adj = softmax(-2 sd), L = lse(-sd) ----------------
__global__ void __launch_bounds__(256)
k_softmax2(const __nv_bfloat16* __restrict__ sda,
           const __nv_bfloat16* __restrict__ sdv,
           __nv_bfloat16* __restrict__ adja,
           __nv_bfloat16* __restrict__ adjv,
           float* __restrict__ La, float* __restrict__ Lv){
  int rowg = blockIdx.x*8 + (threadIdx.x >> 5);
  int lane = threadIdx.x & 31;
  int which = rowg >> 14;
  int row = rowg & (N_-1);
  const __nv_bfloat16* sd = which ? sdv : sda;
  __nv_bfloat16* adj = which ? adjv : adja;
  float* L = which ? Lv : La;
  size_t base = (size_t)row * M_;
  const uint2* src = (const uint2*)(sd + base);
  uint2* dst = (uint2*)(adj + base);

  float v[32];
  float vmin = 3.4e38f;
  #pragma unroll
  for (int j=0;j<8;j++){
    uint2 pk = src[lane + 32*j];
    __nv_bfloat162 p0 = *(__nv_bfloat162*)&pk.x;
    __nv_bfloat162 p1 = *(__nv_bfloat162*)&pk.y;
    float f0 = __low2float(p0), f1 = __high2float(p0);
    float f2 = __low2float(p1), f3 = __high2float(p1);
    v[4*j]=f0; v[4*j+1]=f1; v[4*j+2]=f2; v[4*j+3]=f3;
    vmin = fminf(vmin, fminf(fminf(f0,f1), fminf(f2,f3)));
  }
  float rmin = warpRedMin(vmin);
  float s1 = 0.f, s2 = 0.f;
  #pragma unroll
  for (int k=0;k<32;k++){
    float e = __expf(rmin - v[k]);
    v[k] = e;
    s1 += e; s2 += e*e;
  }
  s1 = warpRedSum(s1);
  s2 = warpRedSum(s2);
  float i2 = 1.0f/s2;
  #pragma unroll
  for (int j=0;j<8;j++){
    float e0=v[4*j], e1=v[4*j+1], e2=v[4*j+2], e3=v[4*j+3];
    __nv_bfloat162 a0 = __floats2bfloat162_rn(e0*e0*i2, e1*e1*i2);
    __nv_bfloat162 a1 = __floats2bfloat162_rn(e2*e2*i2, e3*e3*i2);
    uint2 o; o.x = *(unsigned*)&a0; o.y = *(unsigned*)&a1;
    dst[lane + 32*j] = o;
  }
  if (!lane) L[row] = logf(s1) - rmin;
}

// ---------------- GEMM2 + fused loss epilogue ----------------
// S[i,j] = -(adj_i . sd_j) - L[j]; rowsum += exp(S); diag stores S_ii (log-domain)
__global__ void __launch_bounds__(128, 2)
k_g2(const __nv_bfloat16* __restrict__ adjA, const __nv_bfloat16* __restrict__ adjV,
     const __nv_bfloat16* __restrict__ sdA,  const __nv_bfloat16* __restrict__ sdV,
     const float* __restrict__ La, const float* __restrict__ Lv,
     float* __restrict__ rowsum, float* __restrict__ diag)
{
  extern __shared__ char dsm[];
  uint32_t sbase = (uint32_t)__cvta_generic_to_shared(dsm);
  const int tid = threadIdx.x, lane = tid & 31, warp = tid >> 5;
  const int wm = (warp & 1) * 64, wn = (warp >> 1) * 64;
  const int pair = blockIdx.z >> 5, t = blockIdx.z & 31;
  const __nv_bfloat16* A = pair ? adjV : adjA;
  const __nv_bfloat16* Bm = pair ? sdA : sdV;
  const float* L = pair ? La : Lv;

  const char* Ab = (const char*)A + (long)t*2048 + (long)blockIdx.y * 128 * 65536;
  const char* Bb = (const char*)Bm + (long)t*2048 + (long)blockIdx.x * 128 * 65536;

  float acc[4][8][4];
  #pragma unroll
  for (int a=0;a<4;a++)
    #pragma unroll
    for (int b=0;b<8;b++)
      #pragma unroll
      for (int c=0;c<4;c++) acc[a][b][c]=0.f;

  g_main<16>(sbase, Ab, Bb, 65536, 65536, acc, tid, lane, wm, wn);

  __syncthreads();
  float* Lsm = (float*)dsm;     // 128 floats
  Lsm[tid] = L[(long)(blockIdx.x*128 + tid)*T_ + t];
  __syncthreads();

  const int tr = lane >> 2, tc = (lane & 3) * 2;
  const int batch = pair*T_ + t;
  float* dout = diag + (long)batch * B_;
  float rp[8];
  #pragma unroll
  for (int i=0;i<8;i++) rp[i]=0.f;
  #pragma unroll
  for (int mi=0; mi<4; ++mi){
    int gi0 = blockIdx.y*128 + wm + mi*16 + tr;
    #pragma unroll
    for (int ni=0; ni<8; ++ni){
      int lc = wn + ni*8 + tc;
      int gj = blockIdx.x*128 + lc;
      float L0 = Lsm[lc], L1 = Lsm[lc+1];
      float* a = acc[mi][ni];
      float s00 = -a[0]-L0, s01 = -a[1]-L1;
      float s10 = -a[2]-L0, s11 = -a[3]-L1;
      rp[mi*2]   += __expf(s00) + __expf(s01);
      rp[mi*2+1] += __expf(s10) + __expf(s11);
      if (gj   == gi0)   dout[gi0]   = s00;
      if (gj+1 == gi0)   dout[gi0]   = s01;
      if (gj   == gi0+8) dout[gi0+8] = s10;
      if (gj+1 == gi0+8) dout[gi0+8] = s11;
    }
  }
  #pragma unroll
  for (int i=0;i<8;i++){
    rp[i] += __shfl_xor_sync(0xffffffffu, rp[i], 1);
    rp[i] += __shfl_xor_sync(0xffffffffu, rp[i], 2);
  }
  __syncthreads();
  float* part = (float*)dsm + 128;
  int ng = warp >> 1;
  if ((lane & 3) == 0){
    #pragma unroll
    for (int mi=0; mi<4; ++mi){
      int r = wm + mi*16 + tr;
      part[r*2 + ng]     = rp[mi*2];
      part[(r+8)*2 + ng] = rp[mi*2+1];
    }
  }
  __syncthreads();
  {
    float s = part[tid*2] + part[tid*2+1];
    atomicAdd(&rowsum[(long)batch*B_ + blockIdx.y*128 + tid], s);
  }
}

// ---------------- loss partials and final mean ----------------
// term_i = log(rowsum_i) - S_ii  (diag already log-domain)
__global__ void k_loss2(const float* __restrict__ rs, const float* __restrict__ dg,
                        double* __restrict__ part){
  long base = (long)blockIdx.x * B_;
  float term = 0.f;
  #pragma unroll
  for (int h=0; h<2; ++h){
    long i = base + threadIdx.x + h*256;
    term += logf(rs[i]) - dg[i];
  }
  float s = blockSum(term);
  if (threadIdx.x == 0) part[blockIdx.x] = (double)s;
}
__global__ void k_final(const double* __restrict__ part, float* __restrict__ out){
  double s = (threadIdx.x < 64) ? part[threadIdx.x] : 0.0;
  #pragma unroll
  for (int o=16;o>0;o>>=1) s += __shfl_xor_sync(0xffffffffu, s, o);
  __shared__ double sm[2];
  if ((threadIdx.x & 31) == 0) sm[threadIdx.x>>5] = s;
  __syncthreads();
  if (threadIdx.x == 0) out[0] = (float)((sm[0]+sm[1]) / 32768.0);
}

// ---------------- launch ----------------
extern "C" void kernel_launch(void* const* d_in, const int* in_sizes, int n_in,
                              void* d_out, int out_size)
{
  const float* a = (const float*)d_in[0];
  const float* v = (const float*)d_in[1];
  const float* e = (const float*)d_in[2];
  float* out = (float*)d_out;

  __nv_bfloat16 *pa, *pv, *pe, *psa, *psv, *paa, *pav;
  float *pan, *pvn, *pen, *pLa, *pLv, *prs, *pdg;
  double *ppt;
  cudaGetSymbolAddress((void**)&pa,  g_a_bf);
  cudaGetSymbolAddress((void**)&pv,  g_v_bf);
  cudaGetSymbolAddress((void**)&pe,  g_e_bf);
  cudaGetSymbolAddress((void**)&pan, g_an);
  cudaGetSymbolAddress((void**)&pvn, g_vn);
  cudaGetSymbolAddress((void**)&pen, g_en);
  cudaGetSymbolAddress((void**)&psa, g_sd_a);
  cudaGetSymbolAddress((void**)&psv, g_sd_v);
  cudaGetSymbolAddress((void**)&paa, g_adj_a);
  cudaGetSymbolAddress((void**)&pav, g_adj_v);
  cudaGetSymbolAddress((void**)&pLa, g_L_a);
  cudaGetSymbolAddress((void**)&pLv, g_L_v);
  cudaGetSymbolAddress((void**)&prs, g_rowsum);
  cudaGetSymbolAddress((void**)&pdg, g_diag);
  cudaGetSymbolAddress((void**)&ppt, g_part);

  cudaFuncSetAttribute(k_g1, cudaFuncAttributeMaxDynamicSharedMemorySize, SMEM_DYN);
  cudaFuncSetAttribute(k_g2, cudaFuncAttributeMaxDynamicSharedMemorySize, SMEM_DYN);

  k_prep<<<(2*N_+M_)/8, 256>>>(a, v, e, pa, pv, pe, pan, pvn, pen, prs);

  dim3 g1(M_/128, N_/128, 2);
  k_g1<<<g1, 128, SMEM_DYN>>>(pa, pv, pe, psa, psv, pan, pvn, pen);

  k_softmax2<<<2*N_/8, 256>>>(psa, psv, paa, pav, pLa, pLv);

  dim3 g2(B_/128, B_/128, 64);
  k_g2<<<g2, 128, SMEM_DYN>>>(paa, pav, psa, psv, pLa, pLv, prs, pdg);

  k_loss2<<<64, 256>>>(prs, pdg, ppt);
  k_final<<<1, 64>>>(ppt, out);
}

// round 12
// speedup vs baseline: 1.2098x; 1.0949x over previous
#include <cuda_runtime.h>
#include <cuda_fp16.h>
#include <stdint.h>

#define B_ 512
#define T_ 32
#define D_ 512
#define M_ 1024
#define N_ (B_*T_)          // 16384

// ---------------- scratch (fp16 operands) ----------------
__device__ __align__(16) __half g_a_h[N_*D_];
__device__ __align__(16) __half g_v_h[N_*D_];
__device__ __align__(16) __half g_e_h[M_*D_];
__device__ float g_an[N_];
__device__ float g_vn[N_];
__device__ float g_en[M_];
__device__ __align__(16) __half g_sd_a[N_*M_];
__device__ __align__(16) __half g_sd_v[N_*M_];
__device__ __align__(16) __half g_adj_a[N_*M_];
__device__ __align__(16) __half g_adj_v[N_*M_];
__device__ float g_L_a[N_];
__device__ float g_L_v[N_];
__device__ float g_rowsum[2*T_*B_];
__device__ float g_diag[2*T_*B_];     // log-domain S_ii
__device__ double g_part[64];

// ---------------- reduction helpers ----------------
__device__ __forceinline__ float warpRedSum(float v){
  #pragma unroll
  for (int o=16;o>0;o>>=1) v += __shfl_xor_sync(0xffffffffu, v, o);
  return v;
}
__device__ __forceinline__ float warpRedMin(float v){
  #pragma unroll
  for (int o=16;o>0;o>>=1) v = fminf(v, __shfl_xor_sync(0xffffffffu, v, o));
  return v;
}
__device__ float blockSum(float v){
  __shared__ float sm[32]; __shared__ float res;
  int lane = threadIdx.x & 31, w = threadIdx.x >> 5, nw = blockDim.x >> 5;
  v = warpRedSum(v);
  if (!lane) sm[w] = v;
  __syncthreads();
  if (w == 0){
    float t = (lane < nw) ? sm[lane] : 0.f;
    t = warpRedSum(t);
    if (!lane) res = t;
  }
  __syncthreads();
  return res;
}

// ---------------- merged convert + row sq-norm + rowsum zeroing ----------------
__global__ void k_prep(const float* __restrict__ a, const float* __restrict__ v,
                       const float* __restrict__ e,
                       __half* __restrict__ ab, __half* __restrict__ vb,
                       __half* __restrict__ eb,
                       float* __restrict__ an, float* __restrict__ vn,
                       float* __restrict__ en, float* __restrict__ rs){
  if (blockIdx.x < 64){
    int base = blockIdx.x*512 + threadIdx.x;
    rs[base] = 0.f; rs[base+256] = 0.f;
  }
  int row = blockIdx.x*8 + (threadIdx.x >> 5);
  int lane = threadIdx.x & 31;
  const float* x; __half* xb; float* nrm; int r;
  if (row < N_){ x=a; xb=ab; nrm=an; r=row; }
  else if (row < 2*N_){ x=v; xb=vb; nrm=vn; r=row-N_; }
  else { x=e; xb=eb; nrm=en; r=row-2*N_; }
  const float4* src = (const float4*)(x + (size_t)r * D_);
  uint2* dst = (uint2*)(xb + (size_t)r * D_);
  float s = 0.f;
  #pragma unroll
  for (int i=0;i<4;i++){
    float4 f = src[lane + 32*i];
    s += f.x*f.x + f.y*f.y + f.z*f.z + f.w*f.w;
    __half2 h0 = __floats2half2_rn(f.x, f.y);
    __half2 h1 = __floats2half2_rn(f.z, f.w);
    uint2 o; o.x = *(unsigned*)&h0; o.y = *(unsigned*)&h1;
    dst[lane + 32*i] = o;
  }
  s = warpRedSum(s);
  if (!lane) nrm[r] = s;
}

// ---------------- MMA machinery ----------------
__device__ __forceinline__ void cpa16(uint32_t s, const void* g){
  asm volatile("cp.async.cg.shared.global [%0], [%1], 16;" :: "r"(s), "l"(g));
}
__device__ __forceinline__ void ldmx4(uint32_t* r, uint32_t a){
  asm volatile("ldmatrix.sync.aligned.m8n8.x4.shared.b16 {%0,%1,%2,%3}, [%4];"
    : "=r"(r[0]), "=r"(r[1]), "=r"(r[2]), "=r"(r[3]) : "r"(a));
}
// f32 accumulate, f16 inputs
__device__ __forceinline__ void mma_f32(float* c, const uint32_t* a, uint32_t b0, uint32_t b1){
  asm volatile("mma.sync.aligned.m16n8k16.row.col.f32.f16.f16.f32 "
    "{%0,%1,%2,%3}, {%4,%5,%6,%7}, {%8,%9}, {%0,%1,%2,%3};"
    : "+f"(c[0]), "+f"(c[1]), "+f"(c[2]), "+f"(c[3])
    : "r"(a[0]), "r"(a[1]), "r"(a[2]), "r"(a[3]), "r"(b0), "r"(b1));
}
// f16 accumulate (2 regs)
__device__ __forceinline__ void mma_f16(uint32_t* c, const uint32_t* a, uint32_t b0, uint32_t b1){
  asm volatile("mma.sync.aligned.m16n8k16.row.col.f16.f16.f16.f16 "
    "{%0,%1}, {%2,%3,%4,%5}, {%6,%7}, {%0,%1};"
    : "+r"(c[0]), "+r"(c[1])
    : "r"(a[0]), "r"(a[1]), "r"(a[2]), "r"(a[3]), "r"(b0), "r"(b1));
}

#define ABYTES 16384
#define STG 32768

__device__ __forceinline__ void g_load(uint32_t sbase, int st, int ck,
                                       const char* Ab, const char* Bb,
                                       long ldab, long ldbb, int tid){
  uint32_t dA = sbase + (uint32_t)st * STG;
  uint32_t dB = dA + ABYTES;
  long koff = (long)ck * 128;
  #pragma unroll
  for (int i=0;i<8;i++){
    int idx = tid + (i<<7); int r = idx >> 3, c = idx & 7;
    uint32_t off = (uint32_t)(r*128 + ((c ^ (r&7))<<4));
    cpa16(dA + off, Ab + (long)r*ldab + koff + c*16);
  }
  #pragma unroll
  for (int i=0;i<8;i++){
    int idx = tid + (i<<7); int r = idx >> 3, c = idx & 7;
    uint32_t off = (uint32_t)(r*128 + ((c ^ (r&7))<<4));
    cpa16(dB + off, Bb + (long)r*ldbb + koff + c*16);
  }
  asm volatile("cp.async.commit_group;");
}

__device__ __forceinline__ void ld_frags(uint32_t aB, uint32_t bB, int ks,
                                         int wm, int wn, int lane,
                                         uint32_t af[4][4], uint32_t bfr[4][4]){
  #pragma unroll
  for (int mi=0; mi<4; ++mi){
    int row = wm + mi*16 + (lane & 15);
    int ch  = 2*ks + (lane >> 4);
    ldmx4(af[mi], aB + (uint32_t)(row*128 + ((ch ^ (row&7))<<4)));
  }
  #pragma unroll
  for (int p=0; p<4; ++p){
    int row = wn + p*16 + ((lane>>4)<<3) + (lane&7);
    int ch  = 2*ks + ((lane>>3)&1);
    ldmx4(bfr[p], bB + (uint32_t)(row*128 + ((ch ^ (row&7))<<4)));
  }
}

// ---------------- GEMM1: f16 accum, NBUF=2, 3 CTAs/SM ----------------
// sd = fp16(sqrt(max(rn+cn-2*A.E^T,0))), both modalities in z
#define SMEM_G1 (2*STG)    // 64KB
__global__ void __launch_bounds__(128, 3)
k_g1(const __half* __restrict__ A0, const __half* __restrict__ A1,
     const __half* __restrict__ E,
     __half* __restrict__ C0, __half* __restrict__ C1,
     const float* __restrict__ rn0, const float* __restrict__ rn1,
     const float* __restrict__ cn)
{
  extern __shared__ char dsm[];
  uint32_t sbase = (uint32_t)__cvta_generic_to_shared(dsm);
  const int tid = threadIdx.x, lane = tid & 31, warp = tid >> 5;
  const int wm = (warp & 1) * 64, wn = (warp >> 1) * 64;
  const int z = blockIdx.z;
  const __half* A = z ? A1 : A0;
  const float* rn = z ? rn1 : rn0;
  __half* C = z ? C1 : C0;

  const char* Ab = (const char*)A + (long)blockIdx.y * 128 * 1024;
  const char* Bb = (const char*)E + (long)blockIdx.x * 128 * 1024;
  const int KT = 8;   // 512 elems / 64 per chunk

  uint32_t acc[4][8][2];
  #pragma unroll
  for (int a=0;a<4;a++)
    #pragma unroll
    for (int b=0;b<8;b++){ acc[a][b][0]=0u; acc[a][b][1]=0u; }

  g_load(sbase, 0, 0, Ab, Bb, 1024, 1024, tid);
  g_load(sbase, 1, 1, Ab, Bb, 1024, 1024, tid);
  #pragma unroll 2
  for (int kt = 0; kt < KT; ++kt){
    asm volatile("cp.async.wait_group 1;");
    __syncthreads();
    uint32_t aB = sbase + (uint32_t)(kt&1) * STG;
    uint32_t bB = aB + ABYTES;
    uint32_t af[2][4][4], bfr[2][4][4];
    ld_frags(aB, bB, 0, wm, wn, lane, af[0], bfr[0]);
    #pragma unroll
    for (int ks=0; ks<4; ++ks){
      int cur = ks & 1, nxt = cur ^ 1;
      if (ks < 3) ld_frags(aB, bB, ks+1, wm, wn, lane, af[nxt], bfr[nxt]);
      #pragma unroll
      for (int mi=0; mi<4; ++mi)
        #pragma unroll
        for (int ni=0; ni<8; ++ni){
          const uint32_t* bp = bfr[cur][ni>>1];
          uint32_t b0 = (ni&1) ? bp[2] : bp[0];
          uint32_t b1 = (ni&1) ? bp[3] : bp[1];
          mma_f16(acc[mi][ni], af[cur][mi], b0, b1);
        }
    }
    __syncthreads();                 // all reads of buf kt&1 done
    if (kt+2 < KT) g_load(sbase, kt&1, kt+2, Ab, Bb, 1024, 1024, tid);
    else asm volatile("cp.async.commit_group;");
  }

  const int tr = lane >> 2, tc = (lane & 3) * 2;
  #pragma unroll
  for (int mi=0; mi<4; ++mi){
    int r0 = blockIdx.y*128 + wm + mi*16 + tr;
    float rn0v = rn[r0], rn1v = rn[r0+8];
    #pragma unroll
    for (int ni=0; ni<8; ++ni){
      int col = blockIdx.x*128 + wn + ni*8 + tc;
      float c0 = cn[col], c1 = cn[col+1];
      float2 d0 = __half22float2(*(__half2*)&acc[mi][ni][0]);
      float2 d1 = __half22float2(*(__half2*)&acc[mi][ni][1]);
      __half2 o0 = __floats2half2_rn(
          sqrtf(fmaxf(fmaf(-2.f, d0.x, rn0v + c0), 0.f)),
          sqrtf(fmaxf(fmaf(-2.f, d0.y, rn0v + c1), 0.f)));
      __half2 o1 = __floats2half2_rn(
          sqrtf(fmaxf(fmaf(-2.f, d1.x, rn1v + c0), 0.f)),
          sqrtf(fmaxf(fmaf(-2.f, d1.y, rn1v + c1), 0.f)));
      *(__half2*)&C[(long)r0*M_ + col] = o0;
      *(__half2*)&C[(long)(r0+8)*M_ + col] = o1;
    }
  }
}

// ---------------- softmax (warp per row): adj = softmax(-2 sd), L = lse(-sd) ----------------
__global__ void __launch_bounds__(256)
k_softmax2(const __half* __restrict__ sda, const __half* __restrict__ sdv,
           __half* __restrict__ adja, __half* __restrict__ adjv,
           float* __restrict__ La, float* __restrict__ Lv){
  int rowg = blockIdx.x*8 + (threadIdx.x >> 5);
  int lane = threadIdx.x & 31;
  int which = rowg >> 14;
  int row = rowg & (N_-1);
  const __half* sd = which ? sdv : sda;
  __half* adj = which ? adjv : adja;
  float* L = which ? Lv : La;
  size_t base = (size_t)row * M_;
  const uint2* src = (const uint2*)(sd + base);
  uint2* dst = (uint2*)(adj + base);

  float v[32];
  float vmin = 3.4e38f;
  #pragma unroll
  for (int j=0;j<8;j++){
    uint2 pk = src[lane + 32*j];
    float2 f01 = __half22float2(*(__half2*)&pk.x);
    float2 f23 = __half22float2(*(__half2*)&pk.y);
    v[4*j]=f01.x; v[4*j+1]=f01.y; v[4*j+2]=f23.x; v[4*j+3]=f23.y;
    vmin = fminf(vmin, fminf(fminf(f01.x,f01.y), fminf(f23.x,f23.y)));
  }
  float rmin = warpRedMin(vmin);
  float s1 = 0.f, s2 = 0.f;
  #pragma unroll
  for (int k=0;k<32;k++){
    float e = __expf(rmin - v[k]);
    v[k] = e;
    s1 += e; s2 += e*e;
  }
  s1 = warpRedSum(s1);
  s2 = warpRedSum(s2);
  float i2 = 1.0f/s2;
  #pragma unroll
  for (int j=0;j<8;j++){
    __half2 a0 = __floats2half2_rn(v[4*j]*v[4*j]*i2,     v[4*j+1]*v[4*j+1]*i2);
    __half2 a1 = __floats2half2_rn(v[4*j+2]*v[4*j+2]*i2, v[4*j+3]*v[4*j+3]*i2);
    uint2 o; o.x = *(unsigned*)&a0; o.y = *(unsigned*)&a1;
    dst[lane + 32*j] = o;
  }
  if (!lane) L[row] = logf(s1) - rmin;
}

// ---------------- GEMM2 (f32 accum, NBUF=3, 2 CTAs/SM) + fused loss epilogue ----------------
#define SMEM_G2 (3*STG)    // 96KB
__global__ void __launch_bounds__(128, 2)
k_g2(const __half* __restrict__ adjA, const __half* __restrict__ adjV,
     const __half* __restrict__ sdA,  const __half* __restrict__ sdV,
     const float* __restrict__ La, const float* __restrict__ Lv,
     float* __restrict__ rowsum, float* __restrict__ diag)
{
  extern __shared__ char dsm[];
  uint32_t sbase = (uint32_t)__cvta_generic_to_shared(dsm);
  const int tid = threadIdx.x, lane = tid & 31, warp = tid >> 5;
  const int wm = (warp & 1) * 64, wn = (warp >> 1) * 64;
  const int pair = blockIdx.z >> 5, t = blockIdx.z & 31;
  const __half* A = pair ? adjV : adjA;
  const __half* Bm = pair ? sdA : sdV;
  const float* L = pair ? La : Lv;

  const char* Ab = (const char*)A + (long)t*2048 + (long)blockIdx.y * 128 * 65536;
  const char* Bb = (const char*)Bm + (long)t*2048 + (long)blockIdx.x * 128 * 65536;
  const int KT = 16;

  float acc[4][8][4];
  #pragma unroll
  for (int a=0;a<4;a++)
    #pragma unroll
    for (int b=0;b<8;b++)
      #pragma unroll
      for (int c=0;c<4;c++) acc[a][b][c]=0.f;

  g_load(sbase, 0, 0, Ab, Bb, 65536, 65536, tid);
  g_load(sbase, 1, 1, Ab, Bb, 65536, 65536, tid);
  #pragma unroll 3
  for (int kt = 0; kt < KT; ++kt){
    asm volatile("cp.async.wait_group 1;");
    __syncthreads();
    if (kt+2 < KT) g_load(sbase, (kt+2)%3, kt+2, Ab, Bb, 65536, 65536, tid);
    else asm volatile("cp.async.commit_group;");
    uint32_t aB = sbase + (uint32_t)(kt%3) * STG;
    uint32_t bB = aB + ABYTES;
    uint32_t af[2][4][4], bfr[2][4][4];
    ld_frags(aB, bB, 0, wm, wn, lane, af[0], bfr[0]);
    #pragma unroll
    for (int ks=0; ks<4; ++ks){
      int cur = ks & 1, nxt = cur ^ 1;
      if (ks < 3) ld_frags(aB, bB, ks+1, wm, wn, lane, af[nxt], bfr[nxt]);
      #pragma unroll
      for (int mi=0; mi<4; ++mi)
        #pragma unroll
        for (int ni=0; ni<8; ++ni){
          const uint32_t* bp = bfr[cur][ni>>1];
          uint32_t b0 = (ni&1) ? bp[2] : bp[0];
          uint32_t b1 = (ni&1) ? bp[3] : bp[1];
          mma_f32(acc[mi][ni], af[cur][mi], b0, b1);
        }
    }
  }

  __syncthreads();
  float* Lsm = (float*)dsm;
  Lsm[tid] = L[(long)(blockIdx.x*128 + tid)*T_ + t];
  __syncthreads();

  const int tr = lane >> 2, tc = (lane & 3) * 2;
  const int batch = pair*T_ + t;
  float* dout = diag + (long)batch * B_;
  float rp[8];
  #pragma unroll
  for (int i=0;i<8;i++) rp[i]=0.f;
  #pragma unroll
  for (int mi=0; mi<4; ++mi){
    int gi0 = blockIdx.y*128 + wm + mi*16 + tr;
    #pragma unroll
    for (int ni=0; ni<8; ++ni){
      int lc = wn + ni*8 + tc;
      int gj = blockIdx.x*128 + lc;
      float L0 = Lsm[lc], L1 = Lsm[lc+1];
      float* a = acc[mi][ni];
      float s00 = -a[0]-L0, s01 = -a[1]-L1;
      float s10 = -a[2]-L0, s11 = -a[3]-L1;
      rp[mi*2]   += __expf(s00) + __expf(s01);
      rp[mi*2+1] += __expf(s10) + __expf(s11);
      if (gj   == gi0)   dout[gi0]   = s00;
      if (gj+1 == gi0)   dout[gi0]   = s01;
      if (gj   == gi0+8) dout[gi0+8] = s10;
      if (gj+1 == gi0+8) dout[gi0+8] = s11;
    }
  }
  #pragma unroll
  for (int i=0;i<8;i++){
    rp[i] += __shfl_xor_sync(0xffffffffu, rp[i], 1);
    rp[i] += __shfl_xor_sync(0xffffffffu, rp[i], 2);
  }
  __syncthreads();
  float* part = (float*)dsm + 128;
  int ng = warp >> 1;
  if ((lane & 3) == 0){
    #pragma unroll
    for (int mi=0; mi<4; ++mi){
      int r = wm + mi*16 + tr;
      part[r*2 + ng]     = rp[mi*2];
      part[(r+8)*2 + ng] = rp[mi*2+1];
    }
  }
  __syncthreads();
  {
    float s = part[tid*2] + part[tid*2+1];
    atomicAdd(&rowsum[(long)batch*B_ + blockIdx.y*128 + tid], s);
  }
}

// ---------------- loss partials and final mean ----------------
__global__ void k_loss2(const float* __restrict__ rs, const float* __restrict__ dg,
                        double* __restrict__ part){
  long base = (long)blockIdx.x * B_;
  float term = 0.f;
  #pragma unroll
  for (int h=0; h<2; ++h){
    long i = base + threadIdx.x + h*256;
    term += logf(rs[i]) - dg[i];
  }
  float s = blockSum(term);
  if (threadIdx.x == 0) part[blockIdx.x] = (double)s;
}
__global__ void k_final(const double* __restrict__ part, float* __restrict__ out){
  double s = (threadIdx.x < 64) ? part[threadIdx.x] : 0.0;
  #pragma unroll
  for (int o=16;o>0;o>>=1) s += __shfl_xor_sync(0xffffffffu, s, o);
  __shared__ double sm[2];
  if ((threadIdx.x & 31) == 0) sm[threadIdx.x>>5] = s;
  __syncthreads();
  if (threadIdx.x == 0) out[0] = (float)((sm[0]+sm[1]) / 32768.0);
}

// ---------------- launch ----------------
extern "C" void kernel_launch(void* const* d_in, const int* in_sizes, int n_in,
                              void* d_out, int out_size)
{
  const float* a = (const float*)d_in[0];
  const float* v = (const float*)d_in[1];
  const float* e = (const float*)d_in[2];
  float* out = (float*)d_out;

  __half *pa, *pv, *pe, *psa, *psv, *paa, *pav;
  float *pan, *pvn, *pen, *pLa, *pLv, *prs, *pdg;
  double *ppt;
  cudaGetSymbolAddress((void**)&pa,  g_a_h);
  cudaGetSymbolAddress((void**)&pv,  g_v_h);
  cudaGetSymbolAddress((void**)&pe,  g_e_h);
  cudaGetSymbolAddress((void**)&pan, g_an);
  cudaGetSymbolAddress((void**)&pvn, g_vn);
  cudaGetSymbolAddress((void**)&pen, g_en);
  cudaGetSymbolAddress((void**)&psa, g_sd_a);
  cudaGetSymbolAddress((void**)&psv, g_sd_v);
  cudaGetSymbolAddress((void**)&paa, g_adj_a);
  cudaGetSymbolAddress((void**)&pav, g_adj_v);
  cudaGetSymbolAddress((void**)&pLa, g_L_a);
  cudaGetSymbolAddress((void**)&pLv, g_L_v);
  cudaGetSymbolAddress((void**)&prs, g_rowsum);
  cudaGetSymbolAddress((void**)&pdg, g_diag);
  cudaGetSymbolAddress((void**)&ppt, g_part);

  cudaFuncSetAttribute(k_g1, cudaFuncAttributeMaxDynamicSharedMemorySize, SMEM_G1);
  cudaFuncSetAttribute(k_g2, cudaFuncAttributeMaxDynamicSharedMemorySize, SMEM_G2);

  k_prep<<<(2*N_+M_)/8, 256>>>(a, v, e, pa, pv, pe, pan, pvn, pen, prs);

  dim3 g1(M_/128, N_/128, 2);
  k_g1<<<g1, 128, SMEM_G1>>>(pa, pv, pe, psa, psv, pan, pvn, pen);

  k_softmax2<<<2*N_/8, 256>>>(psa, psv, paa, pav, pLa, pLv);

  dim3 g2(B_/128, B_/128, 64);
  k_g2<<<g2, 128, SMEM_G2>>>(paa, pav, psa, psv, pLa, pLv, prs, pdg);

  k_loss2<<<64, 256>>>(prs, pdg, ppt);
  k_final<<<1, 64>>>(ppt, out);
}

// round 13
// speedup vs baseline: 1.2246x; 1.0123x over previous
#include <cuda_runtime.h>
#include <cuda_fp16.h>
#include <stdint.h>

#define B_ 512
#define T_ 32
#define D_ 512
#define M_ 1024
#define N_ (B_*T_)          // 16384

// ---------------- scratch (fp16 operands; sd stored as sd-22) ----------------
__device__ __align__(16) __half g_a_h[N_*D_];
__device__ __align__(16) __half g_v_h[N_*D_];
__device__ __align__(16) __half g_e_h[M_*D_];
__device__ float g_an[N_];
__device__ float g_vn[N_];
__device__ float g_en[M_];
__device__ __align__(16) __half g_sd_a[N_*M_];
__device__ __align__(16) __half g_sd_v[N_*M_];
__device__ __align__(16) __half g_adj_a[N_*M_];
__device__ __align__(16) __half g_adj_v[N_*M_];
__device__ float g_L_a[N_];
__device__ float g_L_v[N_];
__device__ float g_rowsum[2*T_*B_];
__device__ float g_diag[2*T_*B_];     // log-domain S_ii
__device__ double g_part[64];

// ---------------- reduction helpers ----------------
__device__ __forceinline__ float warpRedSum(float v){
  #pragma unroll
  for (int o=16;o>0;o>>=1) v += __shfl_xor_sync(0xffffffffu, v, o);
  return v;
}
__device__ __forceinline__ float warpRedMin(float v){
  #pragma unroll
  for (int o=16;o>0;o>>=1) v = fminf(v, __shfl_xor_sync(0xffffffffu, v, o));
  return v;
}
__device__ float blockSum(float v){
  __shared__ float sm[32]; __shared__ float res;
  int lane = threadIdx.x & 31, w = threadIdx.x >> 5, nw = blockDim.x >> 5;
  v = warpRedSum(v);
  if (!lane) sm[w] = v;
  __syncthreads();
  if (w == 0){
    float t = (lane < nw) ? sm[lane] : 0.f;
    t = warpRedSum(t);
    if (!lane) res = t;
  }
  __syncthreads();
  return res;
}

// ---------------- merged convert + row sq-norm + rowsum zeroing ----------------
__global__ void k_prep(const float* __restrict__ a, const float* __restrict__ v,
                       const float* __restrict__ e,
                       __half* __restrict__ ab, __half* __restrict__ vb,
                       __half* __restrict__ eb,
                       float* __restrict__ an, float* __restrict__ vn,
                       float* __restrict__ en, float* __restrict__ rs){
  if (blockIdx.x < 64){
    int base = blockIdx.x*512 + threadIdx.x;
    rs[base] = 0.f; rs[base+256] = 0.f;
  }
  int row = blockIdx.x*8 + (threadIdx.x >> 5);
  int lane = threadIdx.x & 31;
  const float* x; __half* xb; float* nrm; int r;
  if (row < N_){ x=a; xb=ab; nrm=an; r=row; }
  else if (row < 2*N_){ x=v; xb=vb; nrm=vn; r=row-N_; }
  else { x=e; xb=eb; nrm=en; r=row-2*N_; }
  const float4* src = (const float4*)(x + (size_t)r * D_);
  uint2* dst = (uint2*)(xb + (size_t)r * D_);
  float s = 0.f;
  #pragma unroll
  for (int i=0;i<4;i++){
    float4 f = src[lane + 32*i];
    s += f.x*f.x + f.y*f.y + f.z*f.z + f.w*f.w;
    __half2 h0 = __floats2half2_rn(f.x, f.y);
    __half2 h1 = __floats2half2_rn(f.z, f.w);
    uint2 o; o.x = *(unsigned*)&h0; o.y = *(unsigned*)&h1;
    dst[lane + 32*i] = o;
  }
  s = warpRedSum(s);
  if (!lane) nrm[r] = s;
}

// ---------------- MMA machinery ----------------
__device__ __forceinline__ void cpa16(uint32_t s, const void* g){
  asm volatile("cp.async.cg.shared.global [%0], [%1], 16;" :: "r"(s), "l"(g));
}
__device__ __forceinline__ void ldmx4(uint32_t* r, uint32_t a){
  asm volatile("ldmatrix.sync.aligned.m8n8.x4.shared.b16 {%0,%1,%2,%3}, [%4];"
    : "=r"(r[0]), "=r"(r[1]), "=r"(r[2]), "=r"(r[3]) : "r"(a));
}
// f16 accumulate (2 regs)
__device__ __forceinline__ void mma_f16(uint32_t* c, const uint32_t* a, uint32_t b0, uint32_t b1){
  asm volatile("mma.sync.aligned.m16n8k16.row.col.f16.f16.f16.f16 "
    "{%0,%1}, {%2,%3,%4,%5}, {%6,%7}, {%0,%1};"
    : "+r"(c[0]), "+r"(c[1])
    : "r"(a[0]), "r"(a[1]), "r"(a[2]), "r"(a[3]), "r"(b0), "r"(b1));
}

#define ABYTES 16384
#define STG 32768

__device__ __forceinline__ void g_load(uint32_t sbase, int st, int ck,
                                       const char* Ab, const char* Bb,
                                       long ldab, long ldbb, int tid){
  uint32_t dA = sbase + (uint32_t)st * STG;
  uint32_t dB = dA + ABYTES;
  long koff = (long)ck * 128;
  #pragma unroll
  for (int i=0;i<8;i++){
    int idx = tid + (i<<7); int r = idx >> 3, c = idx & 7;
    uint32_t off = (uint32_t)(r*128 + ((c ^ (r&7))<<4));
    cpa16(dA + off, Ab + (long)r*ldab + koff + c*16);
  }
  #pragma unroll
  for (int i=0;i<8;i++){
    int idx = tid + (i<<7); int r = idx >> 3, c = idx & 7;
    uint32_t off = (uint32_t)(r*128 + ((c ^ (r&7))<<4));
    cpa16(dB + off, Bb + (long)r*ldbb + koff + c*16);
  }
  asm volatile("cp.async.commit_group;");
}

__device__ __forceinline__ void ld_frags(uint32_t aB, uint32_t bB, int ks,
                                         int wm, int wn, int lane,
                                         uint32_t af[4][4], uint32_t bfr[4][4]){
  #pragma unroll
  for (int mi=0; mi<4; ++mi){
    int row = wm + mi*16 + (lane & 15);
    int ch  = 2*ks + (lane >> 4);
    ldmx4(af[mi], aB + (uint32_t)(row*128 + ((ch ^ (row&7))<<4)));
  }
  #pragma unroll
  for (int p=0; p<4; ++p){
    int row = wn + p*16 + ((lane>>4)<<3) + (lane&7);
    int ch  = 2*ks + ((lane>>3)&1);
    ldmx4(bfr[p], bB + (uint32_t)(row*128 + ((ch ^ (row&7))<<4)));
  }
}

// f16-acc mainloop, NBUF=2, two syncs per chunk (load into just-freed buffer).
template<int KT>
__device__ __forceinline__ void g_main16(uint32_t sbase, const char* Ab, const char* Bb,
                                         long ldab, long ldbb,
                                         uint32_t acc[4][8][2], int tid, int lane,
                                         int wm, int wn){
  g_load(sbase, 0, 0, Ab, Bb, ldab, ldbb, tid);
  g_load(sbase, 1, 1, Ab, Bb, ldab, ldbb, tid);
  #pragma unroll 2
  for (int kt = 0; kt < KT; ++kt){
    asm volatile("cp.async.wait_group 1;");
    __syncthreads();
    uint32_t aB = sbase + (uint32_t)(kt&1) * STG;
    uint32_t bB = aB + ABYTES;
    #pragma unroll
    for (int ks=0; ks<4; ++ks){
      uint32_t af[4][4], bfr[4][4];
      ld_frags(aB, bB, ks, wm, wn, lane, af, bfr);
      #pragma unroll
      for (int mi=0; mi<4; ++mi)
        #pragma unroll
        for (int ni=0; ni<8; ++ni){
          const uint32_t* bp = bfr[ni>>1];
          uint32_t b0 = (ni&1) ? bp[2] : bp[0];
          uint32_t b1 = (ni&1) ? bp[3] : bp[1];
          mma_f16(acc[mi][ni], af[mi], b0, b1);
        }
    }
    __syncthreads();
    if (kt+2 < KT) g_load(sbase, kt&1, kt+2, Ab, Bb, ldab, ldbb, tid);
    else asm volatile("cp.async.commit_group;");
  }
}

// ---------------- GEMM1: sd' = fp16(sqrt(max(rn+cn-2*A.E^T,0)) - 22) ----------------
#define SMEM_G (2*STG)    // 64KB
__global__ void __launch_bounds__(128, 3)
k_g1(const __half* __restrict__ A0, const __half* __restrict__ A1,
     const __half* __restrict__ E,
     __half* __restrict__ C0, __half* __restrict__ C1,
     const float* __restrict__ rn0, const float* __restrict__ rn1,
     const float* __restrict__ cn)
{
  extern __shared__ char dsm[];
  uint32_t sbase = (uint32_t)__cvta_generic_to_shared(dsm);
  const int tid = threadIdx.x, lane = tid & 31, warp = tid >> 5;
  const int wm = (warp & 1) * 64, wn = (warp >> 1) * 64;
  const int z = blockIdx.z;
  const __half* A = z ? A1 : A0;
  const float* rn = z ? rn1 : rn0;
  __half* C = z ? C1 : C0;

  const char* Ab = (const char*)A + (long)blockIdx.y * 128 * 1024;
  const char* Bb = (const char*)E + (long)blockIdx.x * 128 * 1024;

  uint32_t acc[4][8][2];
  #pragma unroll
  for (int a=0;a<4;a++)
    #pragma unroll
    for (int b=0;b<8;b++){ acc[a][b][0]=0u; acc[a][b][1]=0u; }

  g_main16<8>(sbase, Ab, Bb, 1024, 1024, acc, tid, lane, wm, wn);

  const int tr = lane >> 2, tc = (lane & 3) * 2;
  #pragma unroll
  for (int mi=0; mi<4; ++mi){
    int r0 = blockIdx.y*128 + wm + mi*16 + tr;
    float rn0v = rn[r0], rn1v = rn[r0+8];
    #pragma unroll
    for (int ni=0; ni<8; ++ni){
      int col = blockIdx.x*128 + wn + ni*8 + tc;
      float c0 = cn[col], c1 = cn[col+1];
      float2 d0 = __half22float2(*(__half2*)&acc[mi][ni][0]);
      float2 d1 = __half22float2(*(__half2*)&acc[mi][ni][1]);
      __half2 o0 = __floats2half2_rn(
          sqrtf(fmaxf(fmaf(-2.f, d0.x, rn0v + c0), 0.f)) - 22.f,
          sqrtf(fmaxf(fmaf(-2.f, d0.y, rn0v + c1), 0.f)) - 22.f);
      __half2 o1 = __floats2half2_rn(
          sqrtf(fmaxf(fmaf(-2.f, d1.x, rn1v + c0), 0.f)) - 22.f,
          sqrtf(fmaxf(fmaf(-2.f, d1.y, rn1v + c1), 0.f)) - 22.f);
      *(__half2*)&C[(long)r0*M_ + col] = o0;
      *(__half2*)&C[(long)(r0+8)*M_ + col] = o1;
    }
  }
}

// ---------------- softmax (warp per row): adj = softmax(-2 sd'), L' = lse(-sd') ----------------
__global__ void __launch_bounds__(256)
k_softmax2(const __half* __restrict__ sda, const __half* __restrict__ sdv,
           __half* __restrict__ adja, __half* __restrict__ adjv,
           float* __restrict__ La, float* __restrict__ Lv){
  int rowg = blockIdx.x*8 + (threadIdx.x >> 5);
  int lane = threadIdx.x & 31;
  int which = rowg >> 14;
  int row = rowg & (N_-1);
  const __half* sd = which ? sdv : sda;
  __half* adj = which ? adjv : adja;
  float* L = which ? Lv : La;
  size_t base = (size_t)row * M_;
  const uint2* src = (const uint2*)(sd + base);
  uint2* dst = (uint2*)(adj + base);

  float v[32];
  float vmin = 3.4e38f;
  #pragma unroll
  for (int j=0;j<8;j++){
    uint2 pk = src[lane + 32*j];
    float2 f01 = __half22float2(*(__half2*)&pk.x);
    float2 f23 = __half22float2(*(__half2*)&pk.y);
    v[4*j]=f01.x; v[4*j+1]=f01.y; v[4*j+2]=f23.x; v[4*j+3]=f23.y;
    vmin = fminf(vmin, fminf(fminf(f01.x,f01.y), fminf(f23.x,f23.y)));
  }
  float rmin = warpRedMin(vmin);
  float s1 = 0.f, s2 = 0.f;
  #pragma unroll
  for (int k=0;k<32;k++){
    float e = __expf(rmin - v[k]);
    v[k] = e;
    s1 += e; s2 += e*e;
  }
  s1 = warpRedSum(s1);
  s2 = warpRedSum(s2);
  float i2 = 1.0f/s2;
  #pragma unroll
  for (int j=0;j<8;j++){
    __half2 a0 = __floats2half2_rn(v[4*j]*v[4*j]*i2,     v[4*j+1]*v[4*j+1]*i2);
    __half2 a1 = __floats2half2_rn(v[4*j+2]*v[4*j+2]*i2, v[4*j+3]*v[4*j+3]*i2);
    uint2 o; o.x = *(unsigned*)&a0; o.y = *(unsigned*)&a1;
    dst[lane + 32*j] = o;
  }
  if (!lane) L[row] = logf(s1) - rmin;   // L' in shifted domain
}

// ---------------- GEMM2 (f16 accum, NBUF=2, 3 CTAs/SM) + fused loss epilogue ----------------
// S[i,j] = -(adj_i . sd'_j) - L'[j]  (== original S; shifts cancel)
__global__ void __launch_bounds__(128, 3)
k_g2(const __half* __restrict__ adjA, const __half* __restrict__ adjV,
     const __half* __restrict__ sdA,  const __half* __restrict__ sdV,
     const float* __restrict__ La, const float* __restrict__ Lv,
     float* __restrict__ rowsum, float* __restrict__ diag)
{
  extern __shared__ char dsm[];
  uint32_t sbase = (uint32_t)__cvta_generic_to_shared(dsm);
  const int tid = threadIdx.x, lane = tid & 31, warp = tid >> 5;
  const int wm = (warp & 1) * 64, wn = (warp >> 1) * 64;
  const int pair = blockIdx.z >> 5, t = blockIdx.z & 31;
  const __half* A = pair ? adjV : adjA;
  const __half* Bm = pair ? sdA : sdV;
  const float* L = pair ? La : Lv;

  const char* Ab = (const char*)A + (long)t*2048 + (long)blockIdx.y * 128 * 65536;
  const char* Bb = (const char*)Bm + (long)t*2048 + (long)blockIdx.x * 128 * 65536;

  uint32_t acc[4][8][2];
  #pragma unroll
  for (int a=0;a<4;a++)
    #pragma unroll
    for (int b=0;b<8;b++){ acc[a][b][0]=0u; acc[a][b][1]=0u; }

  g_main16<16>(sbase, Ab, Bb, 65536, 65536, acc, tid, lane, wm, wn);

  __syncthreads();
  float* Lsm = (float*)dsm;
  Lsm[tid] = L[(long)(blockIdx.x*128 + tid)*T_ + t];
  __syncthreads();

  const int tr = lane >> 2, tc = (lane & 3) * 2;
  const int batch = pair*T_ + t;
  float* dout = diag + (long)batch * B_;
  float rp[8];
  #pragma unroll
  for (int i=0;i<8;i++) rp[i]=0.f;
  #pragma unroll
  for (int mi=0; mi<4; ++mi){
    int gi0 = blockIdx.y*128 + wm + mi*16 + tr;
    #pragma unroll
    for (int ni=0; ni<8; ++ni){
      int lc = wn + ni*8 + tc;
      int gj = blockIdx.x*128 + lc;
      float L0 = Lsm[lc], L1 = Lsm[lc+1];
      float2 d0 = __half22float2(*(__half2*)&acc[mi][ni][0]);
      float2 d1 = __half22float2(*(__half2*)&acc[mi][ni][1]);
      float s00 = -d0.x-L0, s01 = -d0.y-L1;
      float s10 = -d1.x-L0, s11 = -d1.y-L1;
      rp[mi*2]   += __expf(s00) + __expf(s01);
      rp[mi*2+1] += __expf(s10) + __expf(s11);
      if (gj   == gi0)   dout[gi0]   = s00;
      if (gj+1 == gi0)   dout[gi0]   = s01;
      if (gj   == gi0+8) dout[gi0+8] = s10;
      if (gj+1 == gi0+8) dout[gi0+8] = s11;
    }
  }
  #pragma unroll
  for (int i=0;i<8;i++){
    rp[i] += __shfl_xor_sync(0xffffffffu, rp[i], 1);
    rp[i] += __shfl_xor_sync(0xffffffffu, rp[i], 2);
  }
  __syncthreads();
  float* part = (float*)dsm + 128;
  int ng = warp >> 1;
  if ((lane & 3) == 0){
    #pragma unroll
    for (int mi=0; mi<4; ++mi){
      int r = wm + mi*16 + tr;
      part[r*2 + ng]     = rp[mi*2];
      part[(r+8)*2 + ng] = rp[mi*2+1];
    }
  }
  __syncthreads();
  {
    float s = part[tid*2] + part[tid*2+1];
    atomicAdd(&rowsum[(long)batch*B_ + blockIdx.y*128 + tid], s);
  }
}

// ---------------- loss partials and final mean ----------------
__global__ void k_loss2(const float* __restrict__ rs, const float* __restrict__ dg,
                        double* __restrict__ part){
  long base = (long)blockIdx.x * B_;
  float term = 0.f;
  #pragma unroll
  for (int h=0; h<2; ++h){
    long i = base + threadIdx.x + h*256;
    term += logf(rs[i]) - dg[i];
  }
  float s = blockSum(term);
  if (threadIdx.x == 0) part[blockIdx.x] = (double)s;
}
__global__ void k_final(const double* __restrict__ part, float* __restrict__ out){
  double s = (threadIdx.x < 64) ? part[threadIdx.x] : 0.0;
  #pragma unroll
  for (int o=16;o>0;o>>=1) s += __shfl_xor_sync(0xffffffffu, s, o);
  __shared__ double sm[2];
  if ((threadIdx.x & 31) == 0) sm[threadIdx.x>>5] = s;
  __syncthreads();
  if (threadIdx.x == 0) out[0] = (float)((sm[0]+sm[1]) / 32768.0);
}

// ---------------- launch ----------------
extern "C" void kernel_launch(void* const* d_in, const int* in_sizes, int n_in,
                              void* d_out, int out_size)
{
  const float* a = (const float*)d_in[0];
  const float* v = (const float*)d_in[1];
  const float* e = (const float*)d_in[2];
  float* out = (float*)d_out;

  __half *pa, *pv, *pe, *psa, *psv, *paa, *pav;
  float *pan, *pvn, *pen, *pLa, *pLv, *prs, *pdg;
  double *ppt;
  cudaGetSymbolAddress((void**)&pa,  g_a_h);
  cudaGetSymbolAddress((void**)&pv,  g_v_h);
  cudaGetSymbolAddress((void**)&pe,  g_e_h);
  cudaGetSymbolAddress((void**)&pan, g_an);
  cudaGetSymbolAddress((void**)&pvn, g_vn);
  cudaGetSymbolAddress((void**)&pen, g_en);
  cudaGetSymbolAddress((void**)&psa, g_sd_a);
  cudaGetSymbolAddress((void**)&psv, g_sd_v);
  cudaGetSymbolAddress((void**)&paa, g_adj_a);
  cudaGetSymbolAddress((void**)&pav, g_adj_v);
  cudaGetSymbolAddress((void**)&pLa, g_L_a);
  cudaGetSymbolAddress((void**)&pLv, g_L_v);
  cudaGetSymbolAddress((void**)&prs, g_rowsum);
  cudaGetSymbolAddress((void**)&pdg, g_diag);
  cudaGetSymbolAddress((void**)&ppt, g_part);

  cudaFuncSetAttribute(k_g1, cudaFuncAttributeMaxDynamicSharedMemorySize, SMEM_G);
  cudaFuncSetAttribute(k_g2, cudaFuncAttributeMaxDynamicSharedMemorySize, SMEM_G);

  k_prep<<<(2*N_+M_)/8, 256>>>(a, v, e, pa, pv, pe, pan, pvn, pen, prs);

  dim3 g1(M_/128, N_/128, 2);
  k_g1<<<g1, 128, SMEM_G>>>(pa, pv, pe, psa, psv, pan, pvn, pen);

  k_softmax2<<<2*N_/8, 256>>>(psa, psv, paa, pav, pLa, pLv);

  dim3 g2(B_/128, B_/128, 64);
  k_g2<<<g2, 128, SMEM_G>>>(paa, pav, psa, psv, pLa, pLv, prs, pdg);

  k_loss2<<<64, 256>>>(prs, pdg, ppt);
  k_final<<<1, 64>>>(ppt, out);
}

// round 15
// speedup vs baseline: 1.2347x; 1.0083x over previous
#include <cuda_runtime.h>
#include <cuda_fp16.h>
#include <stdint.h>

#define B_ 512
#define T_ 32
#define D_ 512
#define M_ 1024
#define N_ (B_*T_)          // 16384

// ---------------- scratch (fp16 operands; sd stored as sd-22) ----------------
__device__ __align__(16) __half g_a_h[N_*D_];
__device__ __align__(16) __half g_v_h[N_*D_];
__device__ __align__(16) __half g_e_h[M_*D_];
__device__ float g_an[N_];
__device__ float g_vn[N_];
__device__ float g_en[M_];
__device__ __align__(16) __half g_sd_a[N_*M_];
__device__ __align__(16) __half g_sd_v[N_*M_];
__device__ __align__(16) __half g_adj_a[N_*M_];
__device__ __align__(16) __half g_adj_v[N_*M_];
__device__ float g_L_a[N_];
__device__ float g_L_v[N_];
__device__ float g_rowsum[2*T_*B_];
__device__ float g_diag[2*T_*B_];     // log-domain S_ii
__device__ double g_part[64];

// ---------------- reduction helpers ----------------
__device__ __forceinline__ float warpRedSum(float v){
  #pragma unroll
  for (int o=16;o>0;o>>=1) v += __shfl_xor_sync(0xffffffffu, v, o);
  return v;
}
__device__ __forceinline__ float warpRedMin(float v){
  #pragma unroll
  for (int o=16;o>0;o>>=1) v = fminf(v, __shfl_xor_sync(0xffffffffu, v, o));
  return v;
}
__device__ float blockSum(float v){
  __shared__ float sm[32]; __shared__ float res;
  int lane = threadIdx.x & 31, w = threadIdx.x >> 5, nw = blockDim.x >> 5;
  v = warpRedSum(v);
  if (!lane) sm[w] = v;
  __syncthreads();
  if (w == 0){
    float t = (lane < nw) ? sm[lane] : 0.f;
    t = warpRedSum(t);
    if (!lane) res = t;
  }
  __syncthreads();
  return res;
}

// ---------------- merged convert + row sq-norm + rowsum zeroing ----------------
__global__ void k_prep(const float* __restrict__ a, const float* __restrict__ v,
                       const float* __restrict__ e,
                       __half* __restrict__ ab, __half* __restrict__ vb,
                       __half* __restrict__ eb,
                       float* __restrict__ an, float* __restrict__ vn,
                       float* __restrict__ en, float* __restrict__ rs){
  if (blockIdx.x < 64){
    int base = blockIdx.x*512 + threadIdx.x;
    rs[base] = 0.f; rs[base+256] = 0.f;
  }
  int row = blockIdx.x*8 + (threadIdx.x >> 5);
  int lane = threadIdx.x & 31;
  const float* x; __half* xb; float* nrm; int r;
  if (row < N_){ x=a; xb=ab; nrm=an; r=row; }
  else if (row < 2*N_){ x=v; xb=vb; nrm=vn; r=row-N_; }
  else { x=e; xb=eb; nrm=en; r=row-2*N_; }
  const float4* src = (const float4*)(x + (size_t)r * D_);
  uint2* dst = (uint2*)(xb + (size_t)r * D_);
  float s = 0.f;
  #pragma unroll
  for (int i=0;i<4;i++){
    float4 f = src[lane + 32*i];
    s += f.x*f.x + f.y*f.y + f.z*f.z + f.w*f.w;
    __half2 h0 = __floats2half2_rn(f.x, f.y);
    __half2 h1 = __floats2half2_rn(f.z, f.w);
    uint2 o; o.x = *(unsigned*)&h0; o.y = *(unsigned*)&h1;
    dst[lane + 32*i] = o;
  }
  s = warpRedSum(s);
  if (!lane) nrm[r] = s;
}

// ---------------- MMA machinery ----------------
__device__ __forceinline__ void cpa16(uint32_t s, const void* g){
  asm volatile("cp.async.cg.shared.global [%0], [%1], 16;" :: "r"(s), "l"(g));
}
__device__ __forceinline__ void ldmx4(uint32_t* r, uint32_t a){
  asm volatile("ldmatrix.sync.aligned.m8n8.x4.shared.b16 {%0,%1,%2,%3}, [%4];"
    : "=r"(r[0]), "=r"(r[1]), "=r"(r[2]), "=r"(r[3]) : "r"(a));
}
__device__ __forceinline__ void mma_f16(uint32_t* c, const uint32_t* a, uint32_t b0, uint32_t b1){
  asm volatile("mma.sync.aligned.m16n8k16.row.col.f16.f16.f16.f16 "
    "{%0,%1}, {%2,%3,%4,%5}, {%6,%7}, {%0,%1};"
    : "+r"(c[0]), "+r"(c[1])
    : "r"(a[0]), "r"(a[1]), "r"(a[2]), "r"(a[3]), "r"(b0), "r"(b1));
}

#define ABYTES 16384
#define STG 32768
#define SMEM_G (2*STG + 2048)   // 2 stages + 2KB tail (epilogue vectors + partials)

__device__ __forceinline__ void g_load(uint32_t sbase, int st, int ck,
                                       const char* Ab, const char* Bb,
                                       long ldab, long ldbb, int tid){
  uint32_t dA = sbase + (uint32_t)st * STG;
  uint32_t dB = dA + ABYTES;
  long koff = (long)ck * 128;
  #pragma unroll
  for (int i=0;i<8;i++){
    int idx = tid + (i<<7); int r = idx >> 3, c = idx & 7;
    uint32_t off = (uint32_t)(r*128 + ((c ^ (r&7))<<4));
    cpa16(dA + off, Ab + (long)r*ldab + koff + c*16);
  }
  #pragma unroll
  for (int i=0;i<8;i++){
    int idx = tid + (i<<7); int r = idx >> 3, c = idx & 7;
    uint32_t off = (uint32_t)(r*128 + ((c ^ (r&7))<<4));
    cpa16(dB + off, Bb + (long)r*ldbb + koff + c*16);
  }
  asm volatile("cp.async.commit_group;");
}

// interleaved fragment loads: first-MMA operands (af0, bfr0) complete earliest
__device__ __forceinline__ void ld_frags(uint32_t aB, uint32_t bB, int ks,
                                         int wm, int wn, int lane,
                                         uint32_t af[4][4], uint32_t bfr[4][4]){
  int arow = (lane & 15), ach = 2*ks + (lane >> 4);
  int brow = ((lane>>4)<<3) + (lane&7), bch = 2*ks + ((lane>>3)&1);
  {
    int row = wm + arow;
    ldmx4(af[0], aB + (uint32_t)(row*128 + ((ach ^ (row&7))<<4)));
  }
  {
    int row = wn + brow;
    ldmx4(bfr[0], bB + (uint32_t)(row*128 + ((bch ^ (row&7))<<4)));
  }
  {
    int row = wn + 16 + brow;
    ldmx4(bfr[1], bB + (uint32_t)(row*128 + ((bch ^ (row&7))<<4)));
  }
  #pragma unroll
  for (int mi=1; mi<4; ++mi){
    int row = wm + mi*16 + arow;
    ldmx4(af[mi], aB + (uint32_t)(row*128 + ((ach ^ (row&7))<<4)));
  }
  #pragma unroll
  for (int p=2; p<4; ++p){
    int row = wn + p*16 + brow;
    ldmx4(bfr[p], bB + (uint32_t)(row*128 + ((bch ^ (row&7))<<4)));
  }
}

template<int KT>
__device__ __forceinline__ void g_main16(uint32_t sbase, const char* Ab, const char* Bb,
                                         long ldab, long ldbb,
                                         uint32_t acc[4][8][2], int tid, int lane,
                                         int wm, int wn){
  g_load(sbase, 0, 0, Ab, Bb, ldab, ldbb, tid);
  g_load(sbase, 1, 1, Ab, Bb, ldab, ldbb, tid);
  #pragma unroll 2
  for (int kt = 0; kt < KT; ++kt){
    asm volatile("cp.async.wait_group 1;");
    __syncthreads();
    uint32_t aB = sbase + (uint32_t)(kt&1) * STG;
    uint32_t bB = aB + ABYTES;
    #pragma unroll
    for (int ks=0; ks<4; ++ks){
      uint32_t af[4][4], bfr[4][4];
      ld_frags(aB, bB, ks, wm, wn, lane, af, bfr);
      #pragma unroll
      for (int mi=0; mi<4; ++mi)
        #pragma unroll
        for (int ni=0; ni<8; ++ni){
          const uint32_t* bp = bfr[ni>>1];
          uint32_t b0 = (ni&1) ? bp[2] : bp[0];
          uint32_t b1 = (ni&1) ? bp[3] : bp[1];
          mma_f16(acc[mi][ni], af[mi], b0, b1);
        }
    }
    __syncthreads();
    if (kt+2 < KT) g_load(sbase, kt&1, kt+2, Ab, Bb, ldab, ldbb, tid);
    else asm volatile("cp.async.commit_group;");
  }
}

// ---------------- GEMM1: sd' = fp16(sqrt(max(rn+cn-2*A.E^T,0)) - 22) ----------------
__global__ void __launch_bounds__(128, 3)
k_g1(const __half* __restrict__ A0, const __half* __restrict__ A1,
     const __half* __restrict__ E,
     __half* __restrict__ C0, __half* __restrict__ C1,
     const float* __restrict__ rn0, const float* __restrict__ rn1,
     const float* __restrict__ cn)
{
  extern __shared__ char dsm[];
  uint32_t sbase = (uint32_t)__cvta_generic_to_shared(dsm);
  float* vecs = (float*)(dsm + 2*STG);   // [0:128) rn, [128:256) cn (1KB of 2KB tail)
  const int tid = threadIdx.x, lane = tid & 31, warp = tid >> 5;
  const int wm = (warp & 1) * 64, wn = (warp >> 1) * 64;
  const int z = blockIdx.z;
  const __half* A = z ? A1 : A0;
  const float* rn = z ? rn1 : rn0;
  __half* C = z ? C1 : C0;

  // preload epilogue vectors (overlaps mainloop; visible via mainloop's syncthreads)
  vecs[tid] = rn[blockIdx.y*128 + tid];
  vecs[128 + tid] = cn[blockIdx.x*128 + tid];

  const char* Ab = (const char*)A + (long)blockIdx.y * 128 * 1024;
  const char* Bb = (const char*)E + (long)blockIdx.x * 128 * 1024;

  uint32_t acc[4][8][2];
  #pragma unroll
  for (int a=0;a<4;a++)
    #pragma unroll
    for (int b=0;b<8;b++){ acc[a][b][0]=0u; acc[a][b][1]=0u; }

  g_main16<8>(sbase, Ab, Bb, 1024, 1024, acc, tid, lane, wm, wn);
  __syncthreads();

  const int tr = lane >> 2, tc = (lane & 3) * 2;
  #pragma unroll
  for (int mi=0; mi<4; ++mi){
    int rl = wm + mi*16 + tr;
    int r0 = blockIdx.y*128 + rl;
    float rn0v = vecs[rl], rn1v = vecs[rl+8];
    #pragma unroll
    for (int ni=0; ni<8; ++ni){
      int lc = wn + ni*8 + tc;
      int col = blockIdx.x*128 + lc;
      float c0 = vecs[128+lc], c1 = vecs[128+lc+1];
      float2 d0 = __half22float2(*(__half2*)&acc[mi][ni][0]);
      float2 d1 = __half22float2(*(__half2*)&acc[mi][ni][1]);
      __half2 o0 = __floats2half2_rn(
          sqrtf(fmaxf(fmaf(-2.f, d0.x, rn0v + c0), 0.f)) - 22.f,
          sqrtf(fmaxf(fmaf(-2.f, d0.y, rn0v + c1), 0.f)) - 22.f);
      __half2 o1 = __floats2half2_rn(
          sqrtf(fmaxf(fmaf(-2.f, d1.x, rn1v + c0), 0.f)) - 22.f,
          sqrtf(fmaxf(fmaf(-2.f, d1.y, rn1v + c1), 0.f)) - 22.f);
      *(__half2*)&C[(long)r0*M_ + col] = o0;
      *(__half2*)&C[(long)(r0+8)*M_ + col] = o1;
    }
  }
}

// ---------------- softmax (warp per row): adj = softmax(-2 sd'), L' = lse(-sd') ----------------
__global__ void __launch_bounds__(256)
k_softmax2(const __half* __restrict__ sda, const __half* __restrict__ sdv,
           __half* __restrict__ adja, __half* __restrict__ adjv,
           float* __restrict__ La, float* __restrict__ Lv){
  int rowg = blockIdx.x*8 + (threadIdx.x >> 5);
  int lane = threadIdx.x & 31;
  int which = rowg >> 14;
  int row = rowg & (N_-1);
  const __half* sd = which ? sdv : sda;
  __half* adj = which ? adjv : adja;
  float* L = which ? Lv : La;
  size_t base = (size_t)row * M_;
  const uint2* src = (const uint2*)(sd + base);
  uint2* dst = (uint2*)(adj + base);

  float v[32];
  float vmin = 3.4e38f;
  #pragma unroll
  for (int j=0;j<8;j++){
    uint2 pk = src[lane + 32*j];
    float2 f01 = __half22float2(*(__half2*)&pk.x);
    float2 f23 = __half22float2(*(__half2*)&pk.y);
    v[4*j]=f01.x; v[4*j+1]=f01.y; v[4*j+2]=f23.x; v[4*j+3]=f23.y;
    vmin = fminf(vmin, fminf(fminf(f01.x,f01.y), fminf(f23.x,f23.y)));
  }
  float rmin = warpRedMin(vmin);
  float s1 = 0.f, s2 = 0.f;
  #pragma unroll
  for (int k=0;k<32;k++){
    float e = __expf(rmin - v[k]);
    v[k] = e;
    s1 += e; s2 += e*e;
  }
  s1 = warpRedSum(s1);
  s2 = warpRedSum(s2);
  float i2 = 1.0f/s2;
  #pragma unroll
  for (int j=0;j<8;j++){
    __half2 a0 = __floats2half2_rn(v[4*j]*v[4*j]*i2,     v[4*j+1]*v[4*j+1]*i2);
    __half2 a1 = __floats2half2_rn(v[4*j+2]*v[4*j+2]*i2, v[4*j+3]*v[4*j+3]*i2);
    uint2 o; o.x = *(unsigned*)&a0; o.y = *(unsigned*)&a1;
    dst[lane + 32*j] = o;
  }
  if (!lane) L[row] = logf(s1) - rmin;
}

// ---------------- GEMM2 (f16 accum, 3 CTAs/SM) + fused loss epilogue ----------------
__global__ void __launch_bounds__(128, 3)
k_g2(const __half* __restrict__ adjA, const __half* __restrict__ adjV,
     const __half* __restrict__ sdA,  const __half* __restrict__ sdV,
     const float* __restrict__ La, const float* __restrict__ Lv,
     float* __restrict__ rowsum, float* __restrict__ diag)
{
  extern __shared__ char dsm[];
  uint32_t sbase = (uint32_t)__cvta_generic_to_shared(dsm);
  float* Lsm  = (float*)(dsm + 2*STG);          // 128 floats  [0, 512) of tail
  float* part = (float*)(dsm + 2*STG) + 128;    // 256 floats  [512, 1536) of 2KB tail
  const int tid = threadIdx.x, lane = tid & 31, warp = tid >> 5;
  const int wm = (warp & 1) * 64, wn = (warp >> 1) * 64;
  const int pair = blockIdx.z >> 5, t = blockIdx.z & 31;
  const __half* A = pair ? adjV : adjA;
  const __half* Bm = pair ? sdA : sdV;
  const float* L = pair ? La : Lv;

  // preload L column vector up-front (overlaps mainloop)
  Lsm[tid] = L[(long)(blockIdx.x*128 + tid)*T_ + t];

  const char* Ab = (const char*)A + (long)t*2048 + (long)blockIdx.y * 128 * 65536;
  const char* Bb = (const char*)Bm + (long)t*2048 + (long)blockIdx.x * 128 * 65536;

  uint32_t acc[4][8][2];
  #pragma unroll
  for (int a=0;a<4;a++)
    #pragma unroll
    for (int b=0;b<8;b++){ acc[a][b][0]=0u; acc[a][b][1]=0u; }

  g_main16<16>(sbase, Ab, Bb, 65536, 65536, acc, tid, lane, wm, wn);
  __syncthreads();

  const int tr = lane >> 2, tc = (lane & 3) * 2;
  const int batch = pair*T_ + t;
  float* dout = diag + (long)batch * B_;
  float rp[8];
  #pragma unroll
  for (int i=0;i<8;i++) rp[i]=0.f;
  #pragma unroll
  for (int mi=0; mi<4; ++mi){
    int gi0 = blockIdx.y*128 + wm + mi*16 + tr;
    #pragma unroll
    for (int ni=0; ni<8; ++ni){
      int lc = wn + ni*8 + tc;
      int gj = blockIdx.x*128 + lc;
      float L0 = Lsm[lc], L1 = Lsm[lc+1];
      float2 d0 = __half22float2(*(__half2*)&acc[mi][ni][0]);
      float2 d1 = __half22float2(*(__half2*)&acc[mi][ni][1]);
      float s00 = -d0.x-L0, s01 = -d0.y-L1;
      float s10 = -d1.x-L0, s11 = -d1.y-L1;
      rp[mi*2]   += __expf(s00) + __expf(s01);
      rp[mi*2+1] += __expf(s10) + __expf(s11);
      if (gj   == gi0)   dout[gi0]   = s00;
      if (gj+1 == gi0)   dout[gi0]   = s01;
      if (gj   == gi0+8) dout[gi0+8] = s10;
      if (gj+1 == gi0+8) dout[gi0+8] = s11;
    }
  }
  #pragma unroll
  for (int i=0;i<8;i++){
    rp[i] += __shfl_xor_sync(0xffffffffu, rp[i], 1);
    rp[i] += __shfl_xor_sync(0xffffffffu, rp[i], 2);
  }
  __syncthreads();
  int ng = warp >> 1;
  if ((lane & 3) == 0){
    #pragma unroll
    for (int mi=0; mi<4; ++mi){
      int r = wm + mi*16 + tr;
      part[r*2 + ng]     = rp[mi*2];
      part[(r+8)*2 + ng] = rp[mi*2+1];
    }
  }
  __syncthreads();
  {
    float s = part[tid*2] + part[tid*2+1];
    atomicAdd(&rowsum[(long)batch*B_ + blockIdx.y*128 + tid], s);
  }
}

// ---------------- loss partials and final mean ----------------
__global__ void k_loss2(const float* __restrict__ rs, const float* __restrict__ dg,
                        double* __restrict__ part){
  long base = (long)blockIdx.x * B_;
  float term = 0.f;
  #pragma unroll
  for (int h=0; h<2; ++h){
    long i = base + threadIdx.x + h*256;
    term += logf(rs[i]) - dg[i];
  }
  float s = blockSum(term);
  if (threadIdx.x == 0) part[blockIdx.x] = (double)s;
}
__global__ void k_final(const double* __restrict__ part, float* __restrict__ out){
  double s = (threadIdx.x < 64) ? part[threadIdx.x] : 0.0;
  #pragma unroll
  for (int o=16;o>0;o>>=1) s += __shfl_xor_sync(0xffffffffu, s, o);
  __shared__ double sm[2];
  if ((threadIdx.x & 31) == 0) sm[threadIdx.x>>5] = s;
  __syncthreads();
  if (threadIdx.x == 0) out[0] = (float)((sm[0]+sm[1]) / 32768.0);
}

// ---------------- launch ----------------
extern "C" void kernel_launch(void* const* d_in, const int* in_sizes, int n_in,
                              void* d_out, int out_size)
{
  const float* a = (const float*)d_in[0];
  const float* v = (const float*)d_in[1];
  const float* e = (const float*)d_in[2];
  float* out = (float*)d_out;

  __half *pa, *pv, *pe, *psa, *psv, *paa, *pav;
  float *pan, *pvn, *pen, *pLa, *pLv, *prs, *pdg;
  double *ppt;
  cudaGetSymbolAddress((void**)&pa,  g_a_h);
  cudaGetSymbolAddress((void**)&pv,  g_v_h);
  cudaGetSymbolAddress((void**)&pe,  g_e_h);
  cudaGetSymbolAddress((void**)&pan, g_an);
  cudaGetSymbolAddress((void**)&pvn, g_vn);
  cudaGetSymbolAddress((void**)&pen, g_en);
  cudaGetSymbolAddress((void**)&psa, g_sd_a);
  cudaGetSymbolAddress((void**)&psv, g_sd_v);
  cudaGetSymbolAddress((void**)&paa, g_adj_a);
  cudaGetSymbolAddress((void**)&pav, g_adj_v);
  cudaGetSymbolAddress((void**)&pLa, g_L_a);
  cudaGetSymbolAddress((void**)&pLv, g_L_v);
  cudaGetSymbolAddress((void**)&prs, g_rowsum);
  cudaGetSymbolAddress((void**)&pdg, g_diag);
  cudaGetSymbolAddress((void**)&ppt, g_part);

  cudaFuncSetAttribute(k_g1, cudaFuncAttributeMaxDynamicSharedMemorySize, SMEM_G);
  cudaFuncSetAttribute(k_g2, cudaFuncAttributeMaxDynamicSharedMemorySize, SMEM_G);

  k_prep<<<(2*N_+M_)/8, 256>>>(a, v, e, pa, pv, pe, pan, pvn, pen, prs);

  dim3 g1(M_/128, N_/128, 2);
  k_g1<<<g1, 128, SMEM_G>>>(pa, pv, pe, psa, psv, pan, pvn, pen);

  k_softmax2<<<2*N_/8, 256>>>(psa, psv, paa, pav, pLa, pLv);

  dim3 g2(B_/128, B_/128, 64);
  k_g2<<<g2, 128, SMEM_G>>>(paa, pav, psa, psv, pLa, pLv, prs, pdg);

  k_loss2<<<64, 256>>>(prs, pdg, ppt);
  k_final<<<1, 64>>>(ppt, out);
}

// round 16
// speedup vs baseline: 1.2349x; 1.0002x over previous
#include <cuda_runtime.h>
#include <cuda_fp16.h>
#include <stdint.h>

#define B_ 512
#define T_ 32
#define D_ 512
#define M_ 1024
#define N_ (B_*T_)          // 16384

// ---------------- scratch (fp16 operands; sd stored as sd-22) ----------------
__device__ __align__(16) __half g_a_h[N_*D_];
__device__ __align__(16) __half g_v_h[N_*D_];
__device__ __align__(16) __half g_e_h[M_*D_];
__device__ float g_an[N_];
__device__ float g_vn[N_];
__device__ float g_en[M_];
__device__ __align__(16) __half g_sd_a[N_*M_];
__device__ __align__(16) __half g_sd_v[N_*M_];
__device__ __align__(16) __half g_adj_a[N_*M_];
__device__ __align__(16) __half g_adj_v[N_*M_];
__device__ float g_L_a[N_];
__device__ float g_L_v[N_];
__device__ float g_rowsum[2*T_*B_];
__device__ float g_diag[2*T_*B_];     // log-domain S_ii
__device__ double g_part[64];

// ---------------- reduction helpers ----------------
__device__ __forceinline__ float warpRedSum(float v){
  #pragma unroll
  for (int o=16;o>0;o>>=1) v += __shfl_xor_sync(0xffffffffu, v, o);
  return v;
}
__device__ __forceinline__ float warpRedMin(float v){
  #pragma unroll
  for (int o=16;o>0;o>>=1) v = fminf(v, __shfl_xor_sync(0xffffffffu, v, o));
  return v;
}
__device__ float blockSum(float v){
  __shared__ float sm[32]; __shared__ float res;
  int lane = threadIdx.x & 31, w = threadIdx.x >> 5, nw = blockDim.x >> 5;
  v = warpRedSum(v);
  if (!lane) sm[w] = v;
  __syncthreads();
  if (w == 0){
    float t = (lane < nw) ? sm[lane] : 0.f;
    t = warpRedSum(t);
    if (!lane) res = t;
  }
  __syncthreads();
  return res;
}

// ---------------- merged convert + row sq-norm + rowsum zeroing ----------------
__global__ void k_prep(const float* __restrict__ a, const float* __restrict__ v,
                       const float* __restrict__ e,
                       __half* __restrict__ ab, __half* __restrict__ vb,
                       __half* __restrict__ eb,
                       float* __restrict__ an, float* __restrict__ vn,
                       float* __restrict__ en, float* __restrict__ rs){
  if (blockIdx.x < 64){
    int base = blockIdx.x*512 + threadIdx.x;
    rs[base] = 0.f; rs[base+256] = 0.f;
  }
  int row = blockIdx.x*8 + (threadIdx.x >> 5);
  int lane = threadIdx.x & 31;
  const float* x; __half* xb; float* nrm; int r;
  if (row < N_){ x=a; xb=ab; nrm=an; r=row; }
  else if (row < 2*N_){ x=v; xb=vb; nrm=vn; r=row-N_; }
  else { x=e; xb=eb; nrm=en; r=row-2*N_; }
  const float4* src = (const float4*)(x + (size_t)r * D_);
  uint2* dst = (uint2*)(xb + (size_t)r * D_);
  float s = 0.f;
  #pragma unroll
  for (int i=0;i<4;i++){
    float4 f = src[lane + 32*i];
    s += f.x*f.x + f.y*f.y + f.z*f.z + f.w*f.w;
    __half2 h0 = __floats2half2_rn(f.x, f.y);
    __half2 h1 = __floats2half2_rn(f.z, f.w);
    uint2 o; o.x = *(unsigned*)&h0; o.y = *(unsigned*)&h1;
    dst[lane + 32*i] = o;
  }
  s = warpRedSum(s);
  if (!lane) nrm[r] = s;
}

// ---------------- MMA machinery ----------------
__device__ __forceinline__ void cpa16(uint32_t s, const void* g){
  asm volatile("cp.async.cg.shared.global [%0], [%1], 16;" :: "r"(s), "l"(g));
}
__device__ __forceinline__ void ldmx4(uint32_t* r, uint32_t a){
  asm volatile("ldmatrix.sync.aligned.m8n8.x4.shared.b16 {%0,%1,%2,%3}, [%4];"
    : "=r"(r[0]), "=r"(r[1]), "=r"(r[2]), "=r"(r[3]) : "r"(a));
}
__device__ __forceinline__ void mma_f16(uint32_t* c, const uint32_t* a, uint32_t b0, uint32_t b1){
  asm volatile("mma.sync.aligned.m16n8k16.row.col.f16.f16.f16.f16 "
    "{%0,%1}, {%2,%3,%4,%5}, {%6,%7}, {%0,%1};"
    : "+r"(c[0]), "+r"(c[1])
    : "r"(a[0]), "r"(a[1]), "r"(a[2]), "r"(a[3]), "r"(b0), "r"(b1));
}

// generic loader: AROWS rows of A + 128 rows of B, both 128B (K=64 fp16) per chunk
template<int AROWS, int STGB>
__device__ __forceinline__ void g_load(uint32_t sbase, int st, int ck,
                                       const char* Ab, const char* Bb,
                                       long ldab, long ldbb, int tid){
  uint32_t dA = sbase + (uint32_t)st * STGB;
  uint32_t dB = dA + AROWS*128;
  long koff = (long)ck * 128;
  #pragma unroll
  for (int i=0;i<AROWS/16;i++){
    int idx = tid + (i<<7); int r = idx >> 3, c = idx & 7;
    uint32_t off = (uint32_t)(r*128 + ((c ^ (r&7))<<4));
    cpa16(dA + off, Ab + (long)r*ldab + koff + c*16);
  }
  #pragma unroll
  for (int i=0;i<8;i++){
    int idx = tid + (i<<7); int r = idx >> 3, c = idx & 7;
    uint32_t off = (uint32_t)(r*128 + ((c ^ (r&7))<<4));
    cpa16(dB + off, Bb + (long)r*ldbb + koff + c*16);
  }
  asm volatile("cp.async.commit_group;");
}

// interleaved fragment loads; MI A-fragments (16 rows each), 4 B-fragments
template<int MI>
__device__ __forceinline__ void ld_frags(uint32_t aB, uint32_t bB, int ks,
                                         int wm, int wn, int lane,
                                         uint32_t af[MI][4], uint32_t bfr[4][4]){
  int arow = (lane & 15), ach = 2*ks + (lane >> 4);
  int brow = ((lane>>4)<<3) + (lane&7), bch = 2*ks + ((lane>>3)&1);
  {
    int row = wm + arow;
    ldmx4(af[0], aB + (uint32_t)(row*128 + ((ach ^ (row&7))<<4)));
  }
  {
    int row = wn + brow;
    ldmx4(bfr[0], bB + (uint32_t)(row*128 + ((bch ^ (row&7))<<4)));
  }
  {
    int row = wn + 16 + brow;
    ldmx4(bfr[1], bB + (uint32_t)(row*128 + ((bch ^ (row&7))<<4)));
  }
  #pragma unroll
  for (int mi=1; mi<MI; ++mi){
    int row = wm + mi*16 + arow;
    ldmx4(af[mi], aB + (uint32_t)(row*128 + ((ach ^ (row&7))<<4)));
  }
  #pragma unroll
  for (int p=2; p<4; ++p){
    int row = wn + p*16 + brow;
    ldmx4(bfr[p], bB + (uint32_t)(row*128 + ((bch ^ (row&7))<<4)));
  }
}

template<int KT, int AROWS, int STGB, int MI>
__device__ __forceinline__ void g_main16(uint32_t sbase, const char* Ab, const char* Bb,
                                         long ldab, long ldbb,
                                         uint32_t acc[MI][8][2], int tid, int lane,
                                         int wm, int wn){
  g_load<AROWS,STGB>(sbase, 0, 0, Ab, Bb, ldab, ldbb, tid);
  g_load<AROWS,STGB>(sbase, 1, 1, Ab, Bb, ldab, ldbb, tid);
  #pragma unroll 2
  for (int kt = 0; kt < KT; ++kt){
    asm volatile("cp.async.wait_group 1;");
    __syncthreads();
    uint32_t aB = sbase + (uint32_t)(kt&1) * STGB;
    uint32_t bB = aB + AROWS*128;
    #pragma unroll
    for (int ks=0; ks<4; ++ks){
      uint32_t af[MI][4], bfr[4][4];
      ld_frags<MI>(aB, bB, ks, wm, wn, lane, af, bfr);
      #pragma unroll
      for (int mi=0; mi<MI; ++mi)
        #pragma unroll
        for (int ni=0; ni<8; ++ni){
          const uint32_t* bp = bfr[ni>>1];
          uint32_t b0 = (ni&1) ? bp[2] : bp[0];
          uint32_t b1 = (ni&1) ? bp[3] : bp[1];
          mma_f16(acc[mi][ni], af[mi], b0, b1);
        }
    }
    __syncthreads();
    if (kt+2 < KT) g_load<AROWS,STGB>(sbase, kt&1, kt+2, Ab, Bb, ldab, ldbb, tid);
    else asm volatile("cp.async.commit_group;");
  }
}

// ---------------- GEMM1: 128x128 tile, 3 CTAs/SM ----------------
#define STG1 32768
#define SMEM_G1 (2*STG1 + 2048)
__global__ void __launch_bounds__(128, 3)
k_g1(const __half* __restrict__ A0, const __half* __restrict__ A1,
     const __half* __restrict__ E,
     __half* __restrict__ C0, __half* __restrict__ C1,
     const float* __restrict__ rn0, const float* __restrict__ rn1,
     const float* __restrict__ cn)
{
  extern __shared__ char dsm[];
  uint32_t sbase = (uint32_t)__cvta_generic_to_shared(dsm);
  float* vecs = (float*)(dsm + 2*STG1);
  const int tid = threadIdx.x, lane = tid & 31, warp = tid >> 5;
  const int wm = (warp & 1) * 64, wn = (warp >> 1) * 64;
  const int z = blockIdx.z;
  const __half* A = z ? A1 : A0;
  const float* rn = z ? rn1 : rn0;
  __half* C = z ? C1 : C0;

  vecs[tid] = rn[blockIdx.y*128 + tid];
  vecs[128 + tid] = cn[blockIdx.x*128 + tid];

  const char* Ab = (const char*)A + (long)blockIdx.y * 128 * 1024;
  const char* Bb = (const char*)E + (long)blockIdx.x * 128 * 1024;

  uint32_t acc[4][8][2];
  #pragma unroll
  for (int a=0;a<4;a++)
    #pragma unroll
    for (int b=0;b<8;b++){ acc[a][b][0]=0u; acc[a][b][1]=0u; }

  g_main16<8,128,STG1,4>(sbase, Ab, Bb, 1024, 1024, acc, tid, lane, wm, wn);
  __syncthreads();

  const int tr = lane >> 2, tc = (lane & 3) * 2;
  #pragma unroll
  for (int mi=0; mi<4; ++mi){
    int rl = wm + mi*16 + tr;
    int r0 = blockIdx.y*128 + rl;
    float rn0v = vecs[rl], rn1v = vecs[rl+8];
    #pragma unroll
    for (int ni=0; ni<8; ++ni){
      int lc = wn + ni*8 + tc;
      int col = blockIdx.x*128 + lc;
      float c0 = vecs[128+lc], c1 = vecs[128+lc+1];
      float2 d0 = __half22float2(*(__half2*)&acc[mi][ni][0]);
      float2 d1 = __half22float2(*(__half2*)&acc[mi][ni][1]);
      __half2 o0 = __floats2half2_rn(
          sqrtf(fmaxf(fmaf(-2.f, d0.x, rn0v + c0), 0.f)) - 22.f,
          sqrtf(fmaxf(fmaf(-2.f, d0.y, rn0v + c1), 0.f)) - 22.f);
      __half2 o1 = __floats2half2_rn(
          sqrtf(fmaxf(fmaf(-2.f, d1.x, rn1v + c0), 0.f)) - 22.f,
          sqrtf(fmaxf(fmaf(-2.f, d1.y, rn1v + c1), 0.f)) - 22.f);
      *(__half2*)&C[(long)r0*M_ + col] = o0;
      *(__half2*)&C[(long)(r0+8)*M_ + col] = o1;
    }
  }
}

// ---------------- softmax (warp per row) ----------------
__global__ void __launch_bounds__(256)
k_softmax2(const __half* __restrict__ sda, const __half* __restrict__ sdv,
           __half* __restrict__ adja, __half* __restrict__ adjv,
           float* __restrict__ La, float* __restrict__ Lv){
  int rowg = blockIdx.x*8 + (threadIdx.x >> 5);
  int lane = threadIdx.x & 31;
  int which = rowg >> 14;
  int row = rowg & (N_-1);
  const __half* sd = which ? sdv : sda;
  __half* adj = which ? adjv : adja;
  float* L = which ? Lv : La;
  size_t base = (size_t)row * M_;
  const uint2* src = (const uint2*)(sd + base);
  uint2* dst = (uint2*)(adj + base);

  float v[32];
  float vmin = 3.4e38f;
  #pragma unroll
  for (int j=0;j<8;j++){
    uint2 pk = src[lane + 32*j];
    float2 f01 = __half22float2(*(__half2*)&pk.x);
    float2 f23 = __half22float2(*(__half2*)&pk.y);
    v[4*j]=f01.x; v[4*j+1]=f01.y; v[4*j+2]=f23.x; v[4*j+3]=f23.y;
    vmin = fminf(vmin, fminf(fminf(f01.x,f01.y), fminf(f23.x,f23.y)));
  }
  float rmin = warpRedMin(vmin);
  float s1 = 0.f, s2 = 0.f;
  #pragma unroll
  for (int k=0;k<32;k++){
    float e = __expf(rmin - v[k]);
    v[k] = e;
    s1 += e; s2 += e*e;
  }
  s1 = warpRedSum(s1);
  s2 = warpRedSum(s2);
  float i2 = 1.0f/s2;
  #pragma unroll
  for (int j=0;j<8;j++){
    __half2 a0 = __floats2half2_rn(v[4*j]*v[4*j]*i2,     v[4*j+1]*v[4*j+1]*i2);
    __half2 a1 = __floats2half2_rn(v[4*j+2]*v[4*j+2]*i2, v[4*j+3]*v[4*j+3]*i2);
    uint2 o; o.x = *(unsigned*)&a0; o.y = *(unsigned*)&a1;
    dst[lane + 32*j] = o;
  }
  if (!lane) L[row] = logf(s1) - rmin;
}

// ---------------- GEMM2: 64x128 tile, 4 CTAs/SM + fused loss epilogue ----------------
#define STG2 24576
#define SMEM_G2 (2*STG2 + 2048)
__global__ void __launch_bounds__(128, 4)
k_g2(const __half* __restrict__ adjA, const __half* __restrict__ adjV,
     const __half* __restrict__ sdA,  const __half* __restrict__ sdV,
     const float* __restrict__ La, const float* __restrict__ Lv,
     float* __restrict__ rowsum, float* __restrict__ diag)
{
  extern __shared__ char dsm[];
  uint32_t sbase = (uint32_t)__cvta_generic_to_shared(dsm);
  float* Lsm  = (float*)(dsm + 2*STG2);          // 128 floats
  float* part = (float*)(dsm + 2*STG2) + 128;    // 128 floats (64 rows x 2)
  const int tid = threadIdx.x, lane = tid & 31, warp = tid >> 5;
  const int wm = (warp & 1) * 32, wn = (warp >> 1) * 64;
  const int pair = blockIdx.z >> 5, t = blockIdx.z & 31;
  const __half* A = pair ? adjV : adjA;
  const __half* Bm = pair ? sdA : sdV;
  const float* L = pair ? La : Lv;

  Lsm[tid] = L[(long)(blockIdx.x*128 + tid)*T_ + t];

  const char* Ab = (const char*)A + (long)t*2048 + (long)blockIdx.y * 64 * 65536;
  const char* Bb = (const char*)Bm + (long)t*2048 + (long)blockIdx.x * 128 * 65536;

  uint32_t acc[2][8][2];
  #pragma unroll
  for (int a=0;a<2;a++)
    #pragma unroll
    for (int b=0;b<8;b++){ acc[a][b][0]=0u; acc[a][b][1]=0u; }

  g_main16<16,64,STG2,2>(sbase, Ab, Bb, 65536, 65536, acc, tid, lane, wm, wn);
  __syncthreads();

  const int tr = lane >> 2, tc = (lane & 3) * 2;
  const int batch = pair*T_ + t;
  float* dout = diag + (long)batch * B_;
  float rp[4];
  #pragma unroll
  for (int i=0;i<4;i++) rp[i]=0.f;
  #pragma unroll
  for (int mi=0; mi<2; ++mi){
    int gi0 = blockIdx.y*64 + wm + mi*16 + tr;
    #pragma unroll
    for (int ni=0; ni<8; ++ni){
      int lc = wn + ni*8 + tc;
      int gj = blockIdx.x*128 + lc;
      float L0 = Lsm[lc], L1 = Lsm[lc+1];
      float2 d0 = __half22float2(*(__half2*)&acc[mi][ni][0]);
      float2 d1 = __half22float2(*(__half2*)&acc[mi][ni][1]);
      float s00 = -d0.x-L0, s01 = -d0.y-L1;
      float s10 = -d1.x-L0, s11 = -d1.y-L1;
      rp[mi*2]   += __expf(s00) + __expf(s01);
      rp[mi*2+1] += __expf(s10) + __expf(s11);
      if (gj   == gi0)   dout[gi0]   = s00;
      if (gj+1 == gi0)   dout[gi0]   = s01;
      if (gj   == gi0+8) dout[gi0+8] = s10;
      if (gj+1 == gi0+8) dout[gi0+8] = s11;
    }
  }
  #pragma unroll
  for (int i=0;i<4;i++){
    rp[i] += __shfl_xor_sync(0xffffffffu, rp[i], 1);
    rp[i] += __shfl_xor_sync(0xffffffffu, rp[i], 2);
  }
  __syncthreads();
  int ng = warp >> 1;
  if ((lane & 3) == 0){
    #pragma unroll
    for (int mi=0; mi<2; ++mi){
      int r = wm + mi*16 + tr;
      part[r*2 + ng]     = rp[mi*2];
      part[(r+8)*2 + ng] = rp[mi*2+1];
    }
  }
  __syncthreads();
  if (tid < 64){
    float s = part[tid*2] + part[tid*2+1];
    atomicAdd(&rowsum[(long)batch*B_ + blockIdx.y*64 + tid], s);
  }
}

// ---------------- loss partials and final mean ----------------
__global__ void k_loss2(const float* __restrict__ rs, const float* __restrict__ dg,
                        double* __restrict__ part){
  long base = (long)blockIdx.x * B_;
  float term = 0.f;
  #pragma unroll
  for (int h=0; h<2; ++h){
    long i = base + threadIdx.x + h*256;
    term += logf(rs[i]) - dg[i];
  }
  float s = blockSum(term);
  if (threadIdx.x == 0) part[blockIdx.x] = (double)s;
}
__global__ void k_final(const double* __restrict__ part, float* __restrict__ out){
  double s = (threadIdx.x < 64) ? part[threadIdx.x] : 0.0;
  #pragma unroll
  for (int o=16;o>0;o>>=1) s += __shfl_xor_sync(0xffffffffu, s, o);
  __shared__ double sm[2];
  if ((threadIdx.x & 31) == 0) sm[threadIdx.x>>5] = s;
  __syncthreads();
  if (threadIdx.x == 0) out[0] = (float)((sm[0]+sm[1]) / 32768.0);
}

// ---------------- launch ----------------
extern "C" void kernel_launch(void* const* d_in, const int* in_sizes, int n_in,
                              void* d_out, int out_size)
{
  const float* a = (const float*)d_in[0];
  const float* v = (const float*)d_in[1];
  const float* e = (const float*)d_in[2];
  float* out = (float*)d_out;

  __half *pa, *pv, *pe, *psa, *psv, *paa, *pav;
  float *pan, *pvn, *pen, *pLa, *pLv, *prs, *pdg;
  double *ppt;
  cudaGetSymbolAddress((void**)&pa,  g_a_h);
  cudaGetSymbolAddress((void**)&pv,  g_v_h);
  cudaGetSymbolAddress((void**)&pe,  g_e_h);
  cudaGetSymbolAddress((void**)&pan, g_an);
  cudaGetSymbolAddress((void**)&pvn, g_vn);
  cudaGetSymbolAddress((void**)&pen, g_en);
  cudaGetSymbolAddress((void**)&psa, g_sd_a);
  cudaGetSymbolAddress((void**)&psv, g_sd_v);
  cudaGetSymbolAddress((void**)&paa, g_adj_a);
  cudaGetSymbolAddress((void**)&pav, g_adj_v);
  cudaGetSymbolAddress((void**)&pLa, g_L_a);
  cudaGetSymbolAddress((void**)&pLv, g_L_v);
  cudaGetSymbolAddress((void**)&prs, g_rowsum);
  cudaGetSymbolAddress((void**)&pdg, g_diag);
  cudaGetSymbolAddress((void**)&ppt, g_part);

  cudaFuncSetAttribute(k_g1, cudaFuncAttributeMaxDynamicSharedMemorySize, SMEM_G1);
  cudaFuncSetAttribute(k_g2, cudaFuncAttributeMaxDynamicSharedMemorySize, SMEM_G2);

  k_prep<<<(2*N_+M_)/8, 256>>>(a, v, e, pa, pv, pe, pan, pvn, pen, prs);

  dim3 g1(M_/128, N_/128, 2);
  k_g1<<<g1, 128, SMEM_G1>>>(pa, pv, pe, psa, psv, pan, pvn, pen);

  k_softmax2<<<2*N_/8, 256>>>(psa, psv, paa, pav, pLa, pLv);

  dim3 g2(B_/128, B_/64, 64);
  k_g2<<<g2, 128, SMEM_G2>>>(paa, pav, psa, psv, pLa, pLv, prs, pdg);

  k_loss2<<<64, 256>>>(prs, pdg, ppt);
  k_final<<<1, 64>>>(ppt, out);
}